// round 11
// baseline (speedup 1.0000x reference)
#include <cuda_runtime.h>
#include <cuda_bf16.h>
#include <cstdint>

typedef uint32_t u32;
typedef uint64_t u64;
typedef unsigned short u16;

// ---------------------------------------------------------------------------
// MLSTMFixD round 11 = R7 base +
//  (1) epilogues fused into step GEMMs via last-CTA counter protocol
//  (2) fragment double-buffering (R7 warp shape preserved: 8 warps, 32x16)
//  (3) h1/h2 ping-pong buffers (required by (1))
// ---------------------------------------------------------------------------

constexpr int T_   = 128;
constexpr int B_   = 256;
constexpr int I_   = 512;
constexpr int H_   = 512;
constexpr int O_   = 5;
constexpr int KLAG = 32;
constexpr int BH   = B_ * H_;
constexpr int N1   = 3 * H_;   // 1536
constexpr int N2   = 4 * H_;   // 2048

constexpr int SMEM_X = 2 * 32768;
constexpr int SMEM_S = 2 * 32768;

// ------------------------- device scratch (static) -------------------------
__device__ __align__(16) u16 g_xhi[T_ * B_ * I_], g_xlo[T_ * B_ * I_];
__device__ __align__(16) u16 g_WxHi[N1 * 512],  g_WxLo[N1 * 512];    // Wmih
__device__ __align__(16) u16 g_W1Hi[N1 * 512],  g_W1Lo[N1 * 512];    // Wmhh
__device__ __align__(16) u16 g_W2Hi[N2 * 1024], g_W2Lo[N2 * 1024];   // [Wih|Whh]
__device__ __align__(16) u16 g_h1hi[2][BH], g_h1lo[2][BH];           // ping-pong
__device__ __align__(16) u16 g_h2hi[2][BH], g_h2lo[2][BH];
__device__ float g_c2[BH];
__device__ float g_sel[BH];
__device__ float g_hist[KLAG][BH];           // circular by (t & 31)
__device__ float g_wd[KLAG][H_];
__device__ float g_bs1[N1];                  // bmih + bmhh
__device__ float g_bs2[N2];                  // bih + bhh
__device__ float g_XW[(size_t)T_ * B_ * N1]; // x @ Wmih^T, streamed
__device__ float g_G1[2][B_ * N1];           // K-split partials
__device__ float g_G2[2][B_ * N2];
__device__ int   g_cnt1[32];                 // [bmIdx*8 + hcg], target 6/step
__device__ int   g_cnt2[32];                 // target 8/step

// ------------------------------- helpers ------------------------------------
__device__ __forceinline__ u32 smem_u32(const void* p) {
    u32 a;
    asm("{ .reg .u64 t; cvta.to.shared.u64 t, %1; cvt.u32.u64 %0, t; }" : "=r"(a) : "l"(p));
    return a;
}
__device__ __forceinline__ void cpasync16(u32 dst, const void* src) {
    asm volatile("cp.async.cg.shared.global [%0], [%1], 16;" :: "r"(dst), "l"(src));
}
#define CP_COMMIT() asm volatile("cp.async.commit_group;" ::: "memory")
#define CP_WAIT0()  asm volatile("cp.async.wait_group 0;" ::: "memory")

#define LDSM4(r, addr) asm volatile(                                           \
    "ldmatrix.sync.aligned.m8n8.x4.shared.b16 {%0,%1,%2,%3}, [%4];"            \
    : "=r"((r)[0]), "=r"((r)[1]), "=r"((r)[2]), "=r"((r)[3]) : "r"(addr))

#define MMA(d, a, b0, b1) asm volatile(                                        \
    "mma.sync.aligned.m16n8k16.row.col.f32.bf16.bf16.f32 "                     \
    "{%0,%1,%2,%3}, {%4,%5,%6,%7}, {%8,%9}, {%0,%1,%2,%3};"                    \
    : "+f"((d)[0]), "+f"((d)[1]), "+f"((d)[2]), "+f"((d)[3])                   \
    : "r"((a)[0]), "r"((a)[1]), "r"((a)[2]), "r"((a)[3]), "r"(b0), "r"(b1))

__device__ __forceinline__ u16 bf16bits(__nv_bfloat16 v) {
    __nv_bfloat16_raw r = *reinterpret_cast<__nv_bfloat16_raw*>(&v);
    return r.x;
}
__device__ __forceinline__ void split1(float a, u16& h, u16& l) {
    __nv_bfloat16 bh = __float2bfloat16_rn(a);
    float r = a - __bfloat162float(bh);
    __nv_bfloat16 bl = __float2bfloat16_rn(r);
    h = bf16bits(bh);
    l = bf16bits(bl);
}
__device__ __forceinline__ void split4(float4 v, u32& h01, u32& h23, u32& l01, u32& l23) {
    u16 h0, l0, h1, l1, h2, l2, h3, l3;
    split1(v.x, h0, l0); split1(v.y, h1, l1);
    split1(v.z, h2, l2); split1(v.w, h3, l3);
    h01 = (u32)h0 | ((u32)h1 << 16);  h23 = (u32)h2 | ((u32)h3 << 16);
    l01 = (u32)l0 | ((u32)l1 << 16);  l23 = (u32)l2 | ((u32)l3 << 16);
}
__device__ __forceinline__ float sigf(float x) { return 1.0f / (1.0f + expf(-x)); }
__device__ __forceinline__ float4 add4(float4 a, float4 b) {
    return make_float4(a.x + b.x, a.y + b.y, a.z + b.z, a.w + b.w);
}

// ------------------------------- init ---------------------------------------
__global__ __launch_bounds__(256) void init_kernel(
    const float* __restrict__ b_d,  const float* __restrict__ x,
    const float* __restrict__ Wmih, const float* __restrict__ Wmhh,
    const float* __restrict__ Wih,  const float* __restrict__ Whh,
    const float* __restrict__ bmih, const float* __restrict__ bmhh,
    const float* __restrict__ bih,  const float* __restrict__ bhh)
{
    const int tid = blockIdx.x * blockDim.x + threadIdx.x;
    const int tot = gridDim.x * blockDim.x;

    const int ngx = T_ * B_ * I_ / 4;
    for (int i = tid; i < ngx; i += tot) {
        float4 v = reinterpret_cast<const float4*>(x)[i];
        u32 h01, h23, l01, l23; split4(v, h01, h23, l01, l23);
        reinterpret_cast<uint2*>(g_xhi)[i] = make_uint2(h01, h23);
        reinterpret_cast<uint2*>(g_xlo)[i] = make_uint2(l01, l23);
    }

    const int ngWx = N1 * 512 / 4;
    for (int i = tid; i < ngWx; i += tot) {
        float4 v = reinterpret_cast<const float4*>(Wmih)[i];
        u32 h01, h23, l01, l23; split4(v, h01, h23, l01, l23);
        reinterpret_cast<uint2*>(g_WxHi)[i] = make_uint2(h01, h23);
        reinterpret_cast<uint2*>(g_WxLo)[i] = make_uint2(l01, l23);
    }
    for (int i = tid; i < ngWx; i += tot) {
        float4 v = reinterpret_cast<const float4*>(Wmhh)[i];
        u32 h01, h23, l01, l23; split4(v, h01, h23, l01, l23);
        reinterpret_cast<uint2*>(g_W1Hi)[i] = make_uint2(h01, h23);
        reinterpret_cast<uint2*>(g_W1Lo)[i] = make_uint2(l01, l23);
    }
    const int ngW2 = N2 * 1024 / 4;
    for (int i = tid; i < ngW2; i += tot) {
        int e = i * 4;
        int n = e >> 10, k = e & 1023;
        const float* src = (k < 512) ? (Wih + (size_t)n * 512 + k)
                                     : (Whh + (size_t)n * 512 + (k - 512));
        float4 v = *reinterpret_cast<const float4*>(src);
        u32 h01, h23, l01, l23; split4(v, h01, h23, l01, l23);
        reinterpret_cast<uint2*>(g_W2Hi)[i] = make_uint2(h01, h23);
        reinterpret_cast<uint2*>(g_W2Lo)[i] = make_uint2(l01, l23);
    }

    for (int i = tid; i < N1; i += tot) g_bs1[i] = bmih[i] + bmhh[i];
    for (int i = tid; i < N2; i += tot) g_bs2[i] = bih[i] + bhh[i];

    float4 z4 = make_float4(0.f, 0.f, 0.f, 0.f);
    for (int i = tid; i < KLAG * BH / 4; i += tot)
        reinterpret_cast<float4*>(&g_hist[0][0])[i] = z4;
    for (int i = tid; i < BH / 4; i += tot) {
        reinterpret_cast<float4*>(g_c2)[i]  = z4;
        reinterpret_cast<float4*>(g_sel)[i] = z4;
        reinterpret_cast<uint2*>(&g_h1hi[0][0])[i] = make_uint2(0u, 0u);
        reinterpret_cast<uint2*>(&g_h1lo[0][0])[i] = make_uint2(0u, 0u);
        reinterpret_cast<uint2*>(&g_h2hi[0][0])[i] = make_uint2(0u, 0u);
        reinterpret_cast<uint2*>(&g_h2lo[0][0])[i] = make_uint2(0u, 0u);
    }
    if (tid < 32) { g_cnt1[tid] = 0; g_cnt2[tid] = 0; }

    if (tid < H_) {
        float d = 0.5f * (1.0f / (1.0f + expf(-b_d[tid])));
        float c = 1.0f;
        for (int j = 1; j <= KLAG; j++) {
            c *= ((float)(j - 1) - d) / (float)j;
            g_wd[j - 1][tid] = c;
        }
    }
}

// ------------------- XW precompute: XW = x @ Wmih^T --------------------------
__global__ __launch_bounds__(256, 2) void gemmx_kernel()
{
    extern __shared__ __align__(128) char smem[];
    const u32 sb  = smem_u32(smem);
    const int tid = threadIdx.x;
    const int wid = tid >> 5, lane = tid & 31;
    const int bn  = blockIdx.x * 64;
    const int bm  = blockIdx.y * 64;

    const int lr  = tid >> 3;
    const int lcu = tid & 7;
    auto load_chunk = [&](int c, int stage) {
        const int k0 = c * 64;
        const u32 base = sb + stage * 32768;
#pragma unroll
        for (int j = 0; j < 2; j++) {
            const int r = lr + j * 32;
            const u32 so = (u32)(r * 128 + ((lcu ^ (r & 7)) << 4));
            const size_t ao = (size_t)(bm + r) * 512 + k0 + lcu * 8;
            const size_t bo = (size_t)(bn + r) * 512 + k0 + lcu * 8;
            cpasync16(base + so,         g_xhi  + ao);
            cpasync16(base + 8192 + so,  g_xlo  + ao);
            cpasync16(base + 16384 + so, g_WxHi + bo);
            cpasync16(base + 24576 + so, g_WxLo + bo);
        }
    };

    const int warp_m = wid & 1;
    const int warp_n = wid >> 1;
    const int arow   = warp_m * 32 + (lane & 15);
    const int akh    = lane >> 4;
    const int asw    = arow & 7;
    const u32 aoff0  = (u32)(arow * 128);
    const u32 aoff1  = (u32)((arow + 16) * 128);
    const int brow   = warp_n * 16 + (lane & 7) + ((lane >> 4) << 3);
    const int bkh    = (lane >> 3) & 1;
    const int bsw    = brow & 7;
    const u32 boff   = (u32)(brow * 128);

    float acc[2][2][4] = {};
    u32 fr[2][6][4];   // [buf][ah0 ah1 al0 al1 bh bl]
    u32 Ah = 0, Al = 0, Bh = 0, Bl = 0;

    auto load_frags = [&](int kk, int fb) {
        const u32 sa  = (((u32)(kk * 2 + akh) ^ (u32)asw) << 4);
        const u32 sbo = (((u32)(kk * 2 + bkh) ^ (u32)bsw) << 4);
        LDSM4(fr[fb][0], Ah + aoff0 + sa);
        LDSM4(fr[fb][1], Ah + aoff1 + sa);
        LDSM4(fr[fb][2], Al + aoff0 + sa);
        LDSM4(fr[fb][3], Al + aoff1 + sa);
        LDSM4(fr[fb][4], Bh + boff + sbo);
        LDSM4(fr[fb][5], Bl + boff + sbo);
    };
    auto do_mmas = [&](int fb) {
#pragma unroll
        for (int nt = 0; nt < 2; nt++) {
            MMA(acc[0][nt], fr[fb][0], fr[fb][4][2 * nt], fr[fb][4][2 * nt + 1]);
            MMA(acc[1][nt], fr[fb][1], fr[fb][4][2 * nt], fr[fb][4][2 * nt + 1]);
            MMA(acc[0][nt], fr[fb][0], fr[fb][5][2 * nt], fr[fb][5][2 * nt + 1]);
            MMA(acc[1][nt], fr[fb][1], fr[fb][5][2 * nt], fr[fb][5][2 * nt + 1]);
            MMA(acc[0][nt], fr[fb][2], fr[fb][4][2 * nt], fr[fb][4][2 * nt + 1]);
            MMA(acc[1][nt], fr[fb][3], fr[fb][4][2 * nt], fr[fb][4][2 * nt + 1]);
        }
    };

    load_chunk(0, 0); CP_COMMIT();
    for (int c = 0; c < 8; c++) {
        CP_WAIT0();
        __syncthreads();
        if (c + 1 < 8) { load_chunk(c + 1, (c + 1) & 1); CP_COMMIT(); }

        Ah = sb + (c & 1) * 32768;
        Al = Ah + 8192;
        Bh = Ah + 16384;
        Bl = Ah + 24576;

        load_frags(0, 0);
#pragma unroll
        for (int kk = 0; kk < 4; kk++) {
            if (kk < 3) load_frags(kk + 1, (kk + 1) & 1);
            do_mmas(kk & 1);
        }
    }

#pragma unroll
    for (int mt = 0; mt < 2; mt++)
#pragma unroll
        for (int nt = 0; nt < 2; nt++) {
            const int gm = bm + warp_m * 32 + mt * 16 + (lane >> 2);
            const int gn = bn + warp_n * 16 + nt * 8 + 2 * (lane & 3);
            __stcs(reinterpret_cast<float2*>(&g_XW[(size_t)gm * N1 + gn]),
                   make_float2(acc[mt][nt][0], acc[mt][nt][1]));
            __stcs(reinterpret_cast<float2*>(&g_XW[(size_t)(gm + 8) * N1 + gn]),
                   make_float2(acc[mt][nt][2], acc[mt][nt][3]));
        }
}

// ------------------- shared GEMM mainloop for step kernels -------------------
// CTA 64x64, 256 thr, 8 warps (warp 32x16), 2-stage cp.async, frag dbuf.
// Writes partials to G[(bm+gm)*ldG + bn+gn].
template <int NC, int LDB, int LDG_>
__device__ __forceinline__ void step_gemm_body(
    u32 sb, int tid, int bn, int bm, int kbase,
    const u16* __restrict__ A0hi, const u16* __restrict__ A0lo,  // k < 512
    const u16* __restrict__ A1hi, const u16* __restrict__ A1lo,  // k >= 512 (may be null)
    const u16* __restrict__ BHi,  const u16* __restrict__ BLo,
    float* __restrict__ G)
{
    const int wid = tid >> 5, lane = tid & 31;
    const int lr  = tid >> 3;
    const int lcu = tid & 7;

    auto load_chunk = [&](int c, int stage) {
        const int k0 = kbase + c * 64;
        const u16* ah; const u16* al; int kloc;
        if (k0 >= 512) { ah = A1hi; al = A1lo; kloc = k0 - 512; }
        else           { ah = A0hi; al = A0lo; kloc = k0;       }
        const u32 base = sb + stage * 32768;
#pragma unroll
        for (int j = 0; j < 2; j++) {
            const int r = lr + j * 32;
            const u32 so = (u32)(r * 128 + ((lcu ^ (r & 7)) << 4));
            const size_t ao = (size_t)(bm + r) * 512 + kloc + lcu * 8;
            const size_t bo = (size_t)(bn + r) * LDB + k0 + lcu * 8;
            cpasync16(base + so,         ah  + ao);
            cpasync16(base + 8192 + so,  al  + ao);
            cpasync16(base + 16384 + so, BHi + bo);
            cpasync16(base + 24576 + so, BLo + bo);
        }
    };

    const int warp_m = wid & 1;
    const int warp_n = wid >> 1;
    const int arow   = warp_m * 32 + (lane & 15);
    const int akh    = lane >> 4;
    const int asw    = arow & 7;
    const u32 aoff0  = (u32)(arow * 128);
    const u32 aoff1  = (u32)((arow + 16) * 128);
    const int brow   = warp_n * 16 + (lane & 7) + ((lane >> 4) << 3);
    const int bkh    = (lane >> 3) & 1;
    const int bsw    = brow & 7;
    const u32 boff   = (u32)(brow * 128);

    float acc[2][2][4] = {};
    u32 fr[2][6][4];
    u32 Ah = 0, Al = 0, Bh = 0, Bl = 0;

    auto load_frags = [&](int kk, int fb) {
        const u32 sa  = (((u32)(kk * 2 + akh) ^ (u32)asw) << 4);
        const u32 sbo = (((u32)(kk * 2 + bkh) ^ (u32)bsw) << 4);
        LDSM4(fr[fb][0], Ah + aoff0 + sa);
        LDSM4(fr[fb][1], Ah + aoff1 + sa);
        LDSM4(fr[fb][2], Al + aoff0 + sa);
        LDSM4(fr[fb][3], Al + aoff1 + sa);
        LDSM4(fr[fb][4], Bh + boff + sbo);
        LDSM4(fr[fb][5], Bl + boff + sbo);
    };
    auto do_mmas = [&](int fb) {
#pragma unroll
        for (int nt = 0; nt < 2; nt++) {
            MMA(acc[0][nt], fr[fb][0], fr[fb][4][2 * nt], fr[fb][4][2 * nt + 1]);
            MMA(acc[1][nt], fr[fb][1], fr[fb][4][2 * nt], fr[fb][4][2 * nt + 1]);
            MMA(acc[0][nt], fr[fb][0], fr[fb][5][2 * nt], fr[fb][5][2 * nt + 1]);
            MMA(acc[1][nt], fr[fb][1], fr[fb][5][2 * nt], fr[fb][5][2 * nt + 1]);
            MMA(acc[0][nt], fr[fb][2], fr[fb][4][2 * nt], fr[fb][4][2 * nt + 1]);
            MMA(acc[1][nt], fr[fb][3], fr[fb][4][2 * nt], fr[fb][4][2 * nt + 1]);
        }
    };

    load_chunk(0, 0); CP_COMMIT();
    for (int c = 0; c < NC; c++) {
        CP_WAIT0();
        __syncthreads();
        if (c + 1 < NC) { load_chunk(c + 1, (c + 1) & 1); CP_COMMIT(); }

        Ah = sb + (c & 1) * 32768;
        Al = Ah + 8192;
        Bh = Ah + 16384;
        Bl = Ah + 24576;

        load_frags(0, 0);
#pragma unroll
        for (int kk = 0; kk < 4; kk++) {
            if (kk < 3) load_frags(kk + 1, (kk + 1) & 1);
            do_mmas(kk & 1);
        }
    }

#pragma unroll
    for (int mt = 0; mt < 2; mt++)
#pragma unroll
        for (int nt = 0; nt < 2; nt++) {
            const int gm = bm + warp_m * 32 + mt * 16 + (lane >> 2);
            const int gn = bn + warp_n * 16 + nt * 8 + 2 * (lane & 3);
            *reinterpret_cast<float2*>(&G[(size_t)gm * LDG_ + gn]) =
                make_float2(acc[mt][nt][0], acc[mt][nt][1]);
            *reinterpret_cast<float2*>(&G[(size_t)(gm + 8) * LDG_ + gn]) =
                make_float2(acc[mt][nt][2], acc[mt][nt][3]);
        }
}

// ---------------- step1: h1 @ Wmhh^T + fused mLSTM epilogue ------------------
// grid (24, 4, 2). Counter group (bmIdx, hcg=bnT&7): 3 gates x 2 kz = 6 arrivals.
__global__ __launch_bounds__(256, 2) void step1_kernel(int t)
{
    extern __shared__ __align__(128) char smem[];
    const u32 sb  = smem_u32(smem);
    const int tid = threadIdx.x;
    const int bnT = blockIdx.x;
    const int bmT = blockIdx.y;
    const int kz  = blockIdx.z;
    const int p0  = t & 1, p1 = (t + 1) & 1;

    step_gemm_body<4, 512, N1>(sb, tid, bnT * 64, bmT * 64, kz * 256,
                               g_h1hi[p0], g_h1lo[p0], nullptr, nullptr,
                               g_W1Hi, g_W1Lo, g_G1[kz]);

    __syncthreads();
    __shared__ int s_old;
    if (tid == 0) {
        __threadfence();
        s_old = atomicAdd(&g_cnt1[bmT * 8 + (bnT & 7)], 1);
    }
    __syncthreads();
    if (s_old != 6 * t + 5) return;

    if (tid == 0) __threadfence();
    __syncthreads();

    // fused mLSTM epilogue for rows [bm, bm+64), hc cols [hcg*64, +64)
    const int bm  = bmT * 64;
    const int hc0 = (bnT & 7) * 64;
    for (int u = tid; u < 1024; u += 256) {
        const int row = u >> 4;
        const int hq  = (u & 15) << 2;
        const int b   = bm + row;
        const int hc  = hc0 + hq;
        const int idx = b * 512 + hc;
        const float* __restrict__ Pa = g_G1[0] + (size_t)b * N1;
        const float* __restrict__ Pb = g_G1[1] + (size_t)b * N1;
        const float* __restrict__ Gx = g_XW + ((size_t)t * B_ + b) * N1;

        float4 gi = add4(add4(*(const float4*)(Pa + hc),
                              *(const float4*)(Pb + hc)),
                         add4(__ldcs((const float4*)(Gx + hc)),
                              *(const float4*)(g_bs1 + hc)));
        float4 go = add4(add4(*(const float4*)(Pa + 512 + hc),
                              *(const float4*)(Pb + 512 + hc)),
                         add4(__ldcs((const float4*)(Gx + 512 + hc)),
                              *(const float4*)(g_bs1 + 512 + hc)));
        float4 gg = add4(add4(*(const float4*)(Pa + 1024 + hc),
                              *(const float4*)(Pb + 1024 + hc)),
                         add4(__ldcs((const float4*)(Gx + 1024 + hc)),
                              *(const float4*)(g_bs1 + 1024 + hc)));

        float4 fs = make_float4(0.f, 0.f, 0.f, 0.f);
#pragma unroll
        for (int j = 1; j <= KLAG; j++) {
            const float4 hv = *(const float4*)(&g_hist[(t - j) & (KLAG - 1)][idx]);
            const float4 wv = *(const float4*)(&g_wd[j - 1][hc]);
            fs.x = fmaf(wv.x, hv.x, fs.x);
            fs.y = fmaf(wv.y, hv.y, fs.y);
            fs.z = fmaf(wv.z, hv.z, fs.z);
            fs.w = fmaf(wv.w, hv.w, fs.w);
        }

        float4 c1;
        c1.x = sigf(gi.x) * tanhf(gg.x) - fs.x;
        c1.y = sigf(gi.y) * tanhf(gg.y) - fs.y;
        c1.z = sigf(gi.z) * tanhf(gg.z) - fs.z;
        c1.w = sigf(gi.w) * tanhf(gg.w) - fs.w;
        *(float4*)(&g_hist[t & (KLAG - 1)][idx]) = c1;

        float4 h1n;
        h1n.x = sigf(go.x) * tanhf(c1.x);
        h1n.y = sigf(go.y) * tanhf(c1.y);
        h1n.z = sigf(go.z) * tanhf(c1.z);
        h1n.w = sigf(go.w) * tanhf(c1.w);

        u32 h01, h23, l01, l23;
        split4(h1n, h01, h23, l01, l23);
        *reinterpret_cast<uint2*>(&g_h1hi[p1][idx]) = make_uint2(h01, h23);
        *reinterpret_cast<uint2*>(&g_h1lo[p1][idx]) = make_uint2(l01, l23);
    }
}

// ---------------- step2: [h1n|h2] @ W2^T + fused LSTM epilogue ---------------
// grid (32, 4, 2). Counter group (bmIdx, hcg=bnT&7): 4 gates x 2 kz = 8 arrivals.
__global__ __launch_bounds__(256, 2) void step2_kernel(const int* __restrict__ length, int t)
{
    extern __shared__ __align__(128) char smem[];
    const u32 sb  = smem_u32(smem);
    const int tid = threadIdx.x;
    const int bnT = blockIdx.x;
    const int bmT = blockIdx.y;
    const int kz  = blockIdx.z;
    const int p0  = t & 1, p1 = (t + 1) & 1;

    step_gemm_body<8, 1024, N2>(sb, tid, bnT * 64, bmT * 64, kz * 512,
                                g_h1hi[p1], g_h1lo[p1], g_h2hi[p0], g_h2lo[p0],
                                g_W2Hi, g_W2Lo, g_G2[kz]);

    __syncthreads();
    __shared__ int s_old;
    if (tid == 0) {
        __threadfence();
        s_old = atomicAdd(&g_cnt2[bmT * 8 + (bnT & 7)], 1);
    }
    __syncthreads();
    if (s_old != 8 * t + 7) return;

    if (tid == 0) __threadfence();
    __syncthreads();

    const int bm  = bmT * 64;
    const int hc0 = (bnT & 7) * 64;
    for (int u = tid; u < 1024; u += 256) {
        const int row = u >> 4;
        const int hq  = (u & 15) << 2;
        const int b   = bm + row;
        const int hc  = hc0 + hq;
        const int idx = b * 512 + hc;
        const float* __restrict__ Pa = g_G2[0] + (size_t)b * N2;
        const float* __restrict__ Pb = g_G2[1] + (size_t)b * N2;

        float4 gi = add4(add4(*(const float4*)(Pa + hc),
                              *(const float4*)(Pb + hc)),
                         *(const float4*)(g_bs2 + hc));
        float4 gf = add4(add4(*(const float4*)(Pa + 512 + hc),
                              *(const float4*)(Pb + 512 + hc)),
                         *(const float4*)(g_bs2 + 512 + hc));
        float4 gg = add4(add4(*(const float4*)(Pa + 1024 + hc),
                              *(const float4*)(Pb + 1024 + hc)),
                         *(const float4*)(g_bs2 + 1024 + hc));
        float4 go = add4(add4(*(const float4*)(Pa + 1536 + hc),
                              *(const float4*)(Pb + 1536 + hc)),
                         *(const float4*)(g_bs2 + 1536 + hc));

        float4 cp = *(const float4*)(&g_c2[idx]);
        float4 cn, hv;
        cn.x = sigf(gf.x) * cp.x + sigf(gi.x) * tanhf(gg.x);
        cn.y = sigf(gf.y) * cp.y + sigf(gi.y) * tanhf(gg.y);
        cn.z = sigf(gf.z) * cp.z + sigf(gi.z) * tanhf(gg.z);
        cn.w = sigf(gf.w) * cp.w + sigf(gi.w) * tanhf(gg.w);
        *(float4*)(&g_c2[idx]) = cn;

        hv.x = tanhf(sigf(go.x) * tanhf(cn.x));
        hv.y = tanhf(sigf(go.y) * tanhf(cn.y));
        hv.z = tanhf(sigf(go.z) * tanhf(cn.z));
        hv.w = tanhf(sigf(go.w) * tanhf(cn.w));

        u32 h01, h23, l01, l23;
        split4(hv, h01, h23, l01, l23);
        *reinterpret_cast<uint2*>(&g_h2hi[p1][idx]) = make_uint2(h01, h23);
        *reinterpret_cast<uint2*>(&g_h2lo[p1][idx]) = make_uint2(l01, l23);
        if (length[b] == t) *(float4*)(&g_sel[idx]) = hv;
    }
}

// ------------------------------- head ---------------------------------------
__global__ __launch_bounds__(128) void head_kernel(
    const float* __restrict__ Wout, const float* __restrict__ bout,
    float* __restrict__ out)
{
    const int warp = (blockIdx.x * blockDim.x + threadIdx.x) >> 5;
    const int lane = threadIdx.x & 31;
    if (warp >= B_) return;

    float p[O_] = {0.f, 0.f, 0.f, 0.f, 0.f};
    for (int h = lane; h < H_; h += 32) {
        float s = g_sel[warp * H_ + h];
#pragma unroll
        for (int o = 0; o < O_; o++) p[o] = fmaf(s, Wout[o * H_ + h], p[o]);
    }
#pragma unroll
    for (int o = 0; o < O_; o++)
#pragma unroll
        for (int off = 16; off > 0; off >>= 1)
            p[o] += __shfl_xor_sync(0xffffffffu, p[o], off);

    if (lane == 0) {
        float l[O_], m = -1e30f;
#pragma unroll
        for (int o = 0; o < O_; o++) { l[o] = p[o] + bout[o]; m = fmaxf(m, l[o]); }
        float s = 0.0f;
#pragma unroll
        for (int o = 0; o < O_; o++) s += expf(l[o] - m);
        float ls = logf(s);
#pragma unroll
        for (int o = 0; o < O_; o++) out[warp * O_ + o] = l[o] - m - ls;
    }
}

// ----------------------------- launcher -------------------------------------
extern "C" void kernel_launch(void* const* d_in, const int* in_sizes, int n_in,
                              void* d_out, int out_size)
{
    const float* x    = (const float*)d_in[0];
    const int*   len  = (const int*)  d_in[1];
    const float* b_d  = (const float*)d_in[2];
    const float* Wmih = (const float*)d_in[3];
    const float* Wmhh = (const float*)d_in[4];
    const float* bmih = (const float*)d_in[5];
    const float* bmhh = (const float*)d_in[6];
    const float* Wih  = (const float*)d_in[7];
    const float* Whh  = (const float*)d_in[8];
    const float* bih  = (const float*)d_in[9];
    const float* bhh  = (const float*)d_in[10];
    const float* Wout = (const float*)d_in[11];
    const float* bout = (const float*)d_in[12];
    float* out = (float*)d_out;

    cudaFuncSetAttribute(gemmx_kernel, cudaFuncAttributeMaxDynamicSharedMemorySize, SMEM_X);
    cudaFuncSetAttribute(step1_kernel, cudaFuncAttributeMaxDynamicSharedMemorySize, SMEM_S);
    cudaFuncSetAttribute(step2_kernel, cudaFuncAttributeMaxDynamicSharedMemorySize, SMEM_S);

    init_kernel<<<1024, 256>>>(b_d, x, Wmih, Wmhh, Wih, Whh, bmih, bmhh, bih, bhh);

    gemmx_kernel<<<dim3(N1 / 64, (T_ * B_) / 64), 256, SMEM_X>>>();

    for (int t = 0; t < T_; t++) {
        step1_kernel<<<dim3(24, 4, 2), 256, SMEM_S>>>(t);
        step2_kernel<<<dim3(32, 4, 2), 256, SMEM_S>>>(len, t);
    }

    head_kernel<<<64, 128>>>(Wout, bout, out);
}

// round 12
// speedup vs baseline: 1.4781x; 1.4781x over previous
#include <cuda_runtime.h>
#include <cuda_bf16.h>
#include <cstdint>

typedef uint32_t u32;
typedef uint64_t u64;
typedef unsigned short u16;

// ---------------------------------------------------------------------------
// MLSTMFixD round 12 = R7 (best passing, 3433us) + PDL overlap:
//  - all step/epi kernels launched with programmaticStreamSerialization
//  - gemms: prefetch weight tiles BEFORE cudaGridDependencySynchronize()
//  - trigger early (gemms: post-mainloop; epis: at entry) so successors
//    overlap our tail. Numerics identical to R7.
// ---------------------------------------------------------------------------

constexpr int T_   = 128;
constexpr int B_   = 256;
constexpr int I_   = 512;
constexpr int H_   = 512;
constexpr int O_   = 5;
constexpr int KLAG = 32;
constexpr int BH   = B_ * H_;
constexpr int N1   = 3 * H_;   // 1536
constexpr int N2   = 4 * H_;   // 2048

constexpr int SMEM_X = 2 * 32768;   // gemmx: 2 stages x 32KB
constexpr int SMEM_S = 2 * 32768;   // step gemms: 2 stages x 32KB

// ------------------------- device scratch (static) -------------------------
__device__ __align__(16) u16 g_xhi[T_ * B_ * I_], g_xlo[T_ * B_ * I_];
__device__ __align__(16) u16 g_WxHi[N1 * 512],  g_WxLo[N1 * 512];    // Wmih
__device__ __align__(16) u16 g_W1Hi[N1 * 512],  g_W1Lo[N1 * 512];    // Wmhh
__device__ __align__(16) u16 g_W2Hi[N2 * 1024], g_W2Lo[N2 * 1024];   // [Wih|Whh]
__device__ __align__(16) u16 g_h1hi[BH], g_h1lo[BH];
__device__ __align__(16) u16 g_h2hi[BH], g_h2lo[BH];
__device__ float g_c2[BH];
__device__ float g_sel[BH];
__device__ float g_hist[KLAG][BH];          // circular by (t & 31)
__device__ float g_wd[KLAG][H_];
__device__ float g_XW[(size_t)T_ * B_ * N1];  // x @ Wmih^T for all t (streamed)
__device__ float g_G1[2][B_ * N1];          // K-split partials
__device__ float g_G2[2][B_ * N2];

// ------------------------------- helpers ------------------------------------
__device__ __forceinline__ u32 smem_u32(const void* p) {
    u32 a;
    asm("{ .reg .u64 t; cvta.to.shared.u64 t, %1; cvt.u32.u64 %0, t; }" : "=r"(a) : "l"(p));
    return a;
}
__device__ __forceinline__ void cpasync16(u32 dst, const void* src) {
    asm volatile("cp.async.cg.shared.global [%0], [%1], 16;" :: "r"(dst), "l"(src));
}
#define CP_COMMIT() asm volatile("cp.async.commit_group;" ::: "memory")
#define CP_WAIT0()  asm volatile("cp.async.wait_group 0;" ::: "memory")

#define LDSM4(r, addr) asm volatile(                                           \
    "ldmatrix.sync.aligned.m8n8.x4.shared.b16 {%0,%1,%2,%3}, [%4];"            \
    : "=r"((r)[0]), "=r"((r)[1]), "=r"((r)[2]), "=r"((r)[3]) : "r"(addr))

#define MMA(d, a, b0, b1) asm volatile(                                        \
    "mma.sync.aligned.m16n8k16.row.col.f32.bf16.bf16.f32 "                     \
    "{%0,%1,%2,%3}, {%4,%5,%6,%7}, {%8,%9}, {%0,%1,%2,%3};"                    \
    : "+f"((d)[0]), "+f"((d)[1]), "+f"((d)[2]), "+f"((d)[3])                   \
    : "r"((a)[0]), "r"((a)[1]), "r"((a)[2]), "r"((a)[3]), "r"(b0), "r"(b1))

__device__ __forceinline__ u16 bf16bits(__nv_bfloat16 v) {
    __nv_bfloat16_raw r = *reinterpret_cast<__nv_bfloat16_raw*>(&v);
    return r.x;
}
__device__ __forceinline__ void split1(float a, u16& h, u16& l) {
    __nv_bfloat16 bh = __float2bfloat16_rn(a);
    float r = a - __bfloat162float(bh);
    __nv_bfloat16 bl = __float2bfloat16_rn(r);
    h = bf16bits(bh);
    l = bf16bits(bl);
}
__device__ __forceinline__ void split4(float4 v, u32& h01, u32& h23, u32& l01, u32& l23) {
    u16 h0, l0, h1, l1, h2, l2, h3, l3;
    split1(v.x, h0, l0); split1(v.y, h1, l1);
    split1(v.z, h2, l2); split1(v.w, h3, l3);
    h01 = (u32)h0 | ((u32)h1 << 16);  h23 = (u32)h2 | ((u32)h3 << 16);
    l01 = (u32)l0 | ((u32)l1 << 16);  l23 = (u32)l2 | ((u32)l3 << 16);
}
__device__ __forceinline__ float sigf(float x) { return 1.0f / (1.0f + expf(-x)); }

// ------------------------------- init ---------------------------------------
__global__ __launch_bounds__(256) void init_kernel(
    const float* __restrict__ b_d,  const float* __restrict__ x,
    const float* __restrict__ Wmih, const float* __restrict__ Wmhh,
    const float* __restrict__ Wih,  const float* __restrict__ Whh)
{
    const int tid = blockIdx.x * blockDim.x + threadIdx.x;
    const int tot = gridDim.x * blockDim.x;

    const int ngx = T_ * B_ * I_ / 4;
    for (int i = tid; i < ngx; i += tot) {
        float4 v = reinterpret_cast<const float4*>(x)[i];
        u32 h01, h23, l01, l23; split4(v, h01, h23, l01, l23);
        reinterpret_cast<uint2*>(g_xhi)[i] = make_uint2(h01, h23);
        reinterpret_cast<uint2*>(g_xlo)[i] = make_uint2(l01, l23);
    }

    const int ngWx = N1 * 512 / 4;
    for (int i = tid; i < ngWx; i += tot) {
        float4 v = reinterpret_cast<const float4*>(Wmih)[i];
        u32 h01, h23, l01, l23; split4(v, h01, h23, l01, l23);
        reinterpret_cast<uint2*>(g_WxHi)[i] = make_uint2(h01, h23);
        reinterpret_cast<uint2*>(g_WxLo)[i] = make_uint2(l01, l23);
    }
    for (int i = tid; i < ngWx; i += tot) {
        float4 v = reinterpret_cast<const float4*>(Wmhh)[i];
        u32 h01, h23, l01, l23; split4(v, h01, h23, l01, l23);
        reinterpret_cast<uint2*>(g_W1Hi)[i] = make_uint2(h01, h23);
        reinterpret_cast<uint2*>(g_W1Lo)[i] = make_uint2(l01, l23);
    }
    const int ngW2 = N2 * 1024 / 4;
    for (int i = tid; i < ngW2; i += tot) {
        int e = i * 4;
        int n = e >> 10, k = e & 1023;
        const float* src = (k < 512) ? (Wih + (size_t)n * 512 + k)
                                     : (Whh + (size_t)n * 512 + (k - 512));
        float4 v = *reinterpret_cast<const float4*>(src);
        u32 h01, h23, l01, l23; split4(v, h01, h23, l01, l23);
        reinterpret_cast<uint2*>(g_W2Hi)[i] = make_uint2(h01, h23);
        reinterpret_cast<uint2*>(g_W2Lo)[i] = make_uint2(l01, l23);
    }

    float4 z4 = make_float4(0.f, 0.f, 0.f, 0.f);
    for (int i = tid; i < KLAG * BH / 4; i += tot)
        reinterpret_cast<float4*>(&g_hist[0][0])[i] = z4;
    for (int i = tid; i < BH / 4; i += tot) {
        reinterpret_cast<float4*>(g_c2)[i]  = z4;
        reinterpret_cast<float4*>(g_sel)[i] = z4;
        reinterpret_cast<uint2*>(g_h1hi)[i] = make_uint2(0u, 0u);
        reinterpret_cast<uint2*>(g_h1lo)[i] = make_uint2(0u, 0u);
        reinterpret_cast<uint2*>(g_h2hi)[i] = make_uint2(0u, 0u);
        reinterpret_cast<uint2*>(g_h2lo)[i] = make_uint2(0u, 0u);
    }

    if (tid < H_) {
        float d = 0.5f * (1.0f / (1.0f + expf(-b_d[tid])));
        float c = 1.0f;
        for (int j = 1; j <= KLAG; j++) {
            c *= ((float)(j - 1) - d) / (float)j;
            g_wd[j - 1][tid] = c;
        }
    }
}

// ------------------- XW precompute: XW = x @ Wmih^T --------------------------
// CTA 64x64, 8 warps (warp 32x16), K=512 in 8 chunks, 2-stage, streaming stores.
__global__ __launch_bounds__(256, 2) void gemmx_kernel()
{
    extern __shared__ __align__(128) char smem[];
    const u32 sb  = smem_u32(smem);
    const int tid = threadIdx.x;
    const int wid = tid >> 5, lane = tid & 31;
    const int bn  = blockIdx.x * 64;
    const int bm  = blockIdx.y * 64;

    const int lr  = tid >> 3;
    const int lcu = tid & 7;
    auto load_chunk = [&](int c, int stage) {
        const int k0 = c * 64;
        const u32 base = sb + stage * 32768;
#pragma unroll
        for (int j = 0; j < 2; j++) {
            const int r = lr + j * 32;
            const u32 so = (u32)(r * 128 + ((lcu ^ (r & 7)) << 4));
            const size_t ao = (size_t)(bm + r) * 512 + k0 + lcu * 8;
            const size_t bo = (size_t)(bn + r) * 512 + k0 + lcu * 8;
            cpasync16(base + so,         g_xhi  + ao);
            cpasync16(base + 8192 + so,  g_xlo  + ao);
            cpasync16(base + 16384 + so, g_WxHi + bo);
            cpasync16(base + 24576 + so, g_WxLo + bo);
        }
    };

    const int warp_m = wid & 1;
    const int warp_n = wid >> 1;
    const int arow   = warp_m * 32 + (lane & 15);
    const int akh    = lane >> 4;
    const int asw    = arow & 7;
    const u32 aoff0  = (u32)(arow * 128);
    const u32 aoff1  = (u32)((arow + 16) * 128);
    const int brow   = warp_n * 16 + (lane & 7) + ((lane >> 4) << 3);
    const int bkh    = (lane >> 3) & 1;
    const int bsw    = brow & 7;
    const u32 boff   = (u32)(brow * 128);

    float acc[2][2][4] = {};

    load_chunk(0, 0); CP_COMMIT();
    for (int c = 0; c < 8; c++) {
        CP_WAIT0();
        __syncthreads();
        if (c + 1 < 8) { load_chunk(c + 1, (c + 1) & 1); CP_COMMIT(); }

        const u32 Ah = sb + (c & 1) * 32768;
        const u32 Al = Ah + 8192;
        const u32 Bh = Ah + 16384;
        const u32 Bl = Ah + 24576;
#pragma unroll
        for (int kk = 0; kk < 4; kk++) {
            const u32 sa  = (((u32)(kk * 2 + akh) ^ (u32)asw) << 4);
            const u32 sbo = (((u32)(kk * 2 + bkh) ^ (u32)bsw) << 4);
            u32 ah0[4], ah1[4], al0[4], al1[4], bh[4], bl[4];
            LDSM4(ah0, Ah + aoff0 + sa);
            LDSM4(ah1, Ah + aoff1 + sa);
            LDSM4(al0, Al + aoff0 + sa);
            LDSM4(al1, Al + aoff1 + sa);
            LDSM4(bh,  Bh + boff + sbo);
            LDSM4(bl,  Bl + boff + sbo);
#pragma unroll
            for (int nt = 0; nt < 2; nt++) {
                MMA(acc[0][nt], ah0, bh[2 * nt], bh[2 * nt + 1]);
                MMA(acc[1][nt], ah1, bh[2 * nt], bh[2 * nt + 1]);
                MMA(acc[0][nt], ah0, bl[2 * nt], bl[2 * nt + 1]);
                MMA(acc[1][nt], ah1, bl[2 * nt], bl[2 * nt + 1]);
                MMA(acc[0][nt], al0, bh[2 * nt], bh[2 * nt + 1]);
                MMA(acc[1][nt], al1, bh[2 * nt], bh[2 * nt + 1]);
            }
        }
    }

    // successor (step1 t=0) may begin launching; its safety is its gridDepSync
    cudaTriggerProgrammaticLaunchCompletion();

#pragma unroll
    for (int mt = 0; mt < 2; mt++)
#pragma unroll
        for (int nt = 0; nt < 2; nt++) {
            const int gm = bm + warp_m * 32 + mt * 16 + (lane >> 2);
            const int gn = bn + warp_n * 16 + nt * 8 + 2 * (lane & 3);
            __stcs(reinterpret_cast<float2*>(&g_XW[(size_t)gm * N1 + gn]),
                   make_float2(acc[mt][nt][0], acc[mt][nt][1]));
            __stcs(reinterpret_cast<float2*>(&g_XW[(size_t)(gm + 8) * N1 + gn]),
                   make_float2(acc[mt][nt][2], acc[mt][nt][3]));
        }
}

// ----------------------- step GEMMs (R7 bodies + PDL) ------------------------
// SET=1: G1[kz][256,1536] = h1 @ Wmhh^T      grid (24, 4, 2)  K=256/CTA, 4 chunks
// SET=2: G2[kz][256,2048] = [h1n|h2] @ W2^T  grid (32, 4, 2)  K=512/CTA, 8 chunks
// CTA 64x64, 256 thr, 8 warps (warp 32x16), 2-stage cp.async.
// PDL: weight tile of chunk 0 prefetched BEFORE gridDepSync (weights are from
// init — transitively complete); A (recurrent state) loaded after the sync.
template <int SET>
__global__ __launch_bounds__(256, 2) void gemm_kernel(int t)
{
    constexpr int NC  = (SET == 1) ? 4 : 8;
    constexpr int ldB = (SET == 2) ? 1024 : 512;
    constexpr int ldG = (SET == 2) ? N2 : N1;

    extern __shared__ __align__(128) char smem[];
    const u32 sb  = smem_u32(smem);
    const int tid = threadIdx.x;
    const int wid = tid >> 5, lane = tid & 31;
    const int bn  = blockIdx.x * 64;
    const int bm  = blockIdx.y * 64;
    const int kz  = blockIdx.z;
    const int kbase = (SET == 1) ? kz * 256 : kz * 512;

    const u16* __restrict__ BHi = (SET == 1) ? g_W1Hi : g_W2Hi;
    const u16* __restrict__ BLo = (SET == 1) ? g_W1Lo : g_W2Lo;
    float* __restrict__ G = (SET == 1) ? g_G1[kz] : g_G2[kz];

    const int lr  = tid >> 3;
    const int lcu = tid & 7;
    auto load_B = [&](int c, int stage) {
        const int k0 = kbase + c * 64;
        const u32 base = sb + stage * 32768;
#pragma unroll
        for (int j = 0; j < 2; j++) {
            const int r = lr + j * 32;
            const u32 so = (u32)(r * 128 + ((lcu ^ (r & 7)) << 4));
            const size_t bo = (size_t)(bn + r) * ldB + k0 + lcu * 8;
            cpasync16(base + 16384 + so, BHi + bo);
            cpasync16(base + 24576 + so, BLo + bo);
        }
    };
    auto load_A = [&](int c, int stage) {
        const int k0 = kbase + c * 64;
        const u16* ah; const u16* al; int kloc;
        if (SET == 2 && k0 >= 512) { ah = g_h2hi; al = g_h2lo; kloc = k0 - 512; }
        else                       { ah = g_h1hi; al = g_h1lo; kloc = k0;       }
        const u32 base = sb + stage * 32768;
#pragma unroll
        for (int j = 0; j < 2; j++) {
            const int r = lr + j * 32;
            const u32 so = (u32)(r * 128 + ((lcu ^ (r & 7)) << 4));
            const size_t ao = (size_t)(bm + r) * 512 + kloc + lcu * 8;
            cpasync16(base + so,        ah + ao);
            cpasync16(base + 8192 + so, al + ao);
        }
    };

    const int warp_m = wid & 1;
    const int warp_n = wid >> 1;
    const int arow   = warp_m * 32 + (lane & 15);
    const int akh    = lane >> 4;
    const int asw    = arow & 7;
    const u32 aoff0  = (u32)(arow * 128);
    const u32 aoff1  = (u32)((arow + 16) * 128);
    const int brow   = warp_n * 16 + (lane & 7) + ((lane >> 4) << 3);
    const int bkh    = (lane >> 3) & 1;
    const int bsw    = brow & 7;
    const u32 boff   = (u32)(brow * 128);

    float acc[2][2][4] = {};

    // ---- PDL prologue: weights first, then wait for predecessor, then A ----
    load_B(0, 0); CP_COMMIT();
    cudaGridDependencySynchronize();
    load_A(0, 0); CP_COMMIT();

    for (int c = 0; c < NC; c++) {
        CP_WAIT0();
        __syncthreads();
        if (c + 1 < NC) { load_A(c + 1, (c + 1) & 1); load_B(c + 1, (c + 1) & 1); CP_COMMIT(); }

        const u32 Ah = sb + (c & 1) * 32768;
        const u32 Al = Ah + 8192;
        const u32 Bh = Ah + 16384;
        const u32 Bl = Ah + 24576;
#pragma unroll
        for (int kk = 0; kk < 4; kk++) {
            const u32 sa  = (((u32)(kk * 2 + akh) ^ (u32)asw) << 4);
            const u32 sbo = (((u32)(kk * 2 + bkh) ^ (u32)bsw) << 4);
            u32 ah0[4], ah1[4], al0[4], al1[4], bh[4], bl[4];
            LDSM4(ah0, Ah + aoff0 + sa);
            LDSM4(ah1, Ah + aoff1 + sa);
            LDSM4(al0, Al + aoff0 + sa);
            LDSM4(al1, Al + aoff1 + sa);
            LDSM4(bh,  Bh + boff + sbo);
            LDSM4(bl,  Bl + boff + sbo);
#pragma unroll
            for (int nt = 0; nt < 2; nt++) {
                MMA(acc[0][nt], ah0, bh[2 * nt], bh[2 * nt + 1]);
                MMA(acc[1][nt], ah1, bh[2 * nt], bh[2 * nt + 1]);
                MMA(acc[0][nt], ah0, bl[2 * nt], bl[2 * nt + 1]);
                MMA(acc[1][nt], ah1, bl[2 * nt], bl[2 * nt + 1]);
                MMA(acc[0][nt], al0, bh[2 * nt], bh[2 * nt + 1]);
                MMA(acc[1][nt], al1, bh[2 * nt], bh[2 * nt + 1]);
            }
        }
    }

    // let the epilogue kernel start launching while we store G
    cudaTriggerProgrammaticLaunchCompletion();

#pragma unroll
    for (int mt = 0; mt < 2; mt++)
#pragma unroll
        for (int nt = 0; nt < 2; nt++) {
            const int gm = bm + warp_m * 32 + mt * 16 + (lane >> 2);
            const int gn = bn + warp_n * 16 + nt * 8 + 2 * (lane & 3);
            *reinterpret_cast<float2*>(&G[(size_t)gm * ldG + gn]) =
                make_float2(acc[mt][nt][0], acc[mt][nt][1]);
            *reinterpret_cast<float2*>(&G[(size_t)(gm + 8) * ldG + gn]) =
                make_float2(acc[mt][nt][2], acc[mt][nt][3]);
        }
}

// --------------------- epilogue 1: mLSTM gates + frac filter -----------------
__global__ __launch_bounds__(256) void epi1_kernel(
    const float* __restrict__ bmih, const float* __restrict__ bmhh, int t)
{
    // trigger immediately: successor gemm2 overlaps its weight prefetch with us
    cudaTriggerProgrammaticLaunchCompletion();
    cudaGridDependencySynchronize();

    const int idx = blockIdx.x * blockDim.x + threadIdx.x;
    const int b = idx >> 9, hc = idx & 511;
    const float* __restrict__ Ga = g_G1[0] + (size_t)b * N1;
    const float* __restrict__ Gb = g_G1[1] + (size_t)b * N1;
    const float* __restrict__ Gx = g_XW + ((size_t)t * B_ + b) * N1;

    float vi = sigf (Ga[hc]        + Gb[hc]        + __ldcs(Gx + hc)        + bmih[hc]        + bmhh[hc]);
    float vo = sigf (Ga[512 + hc]  + Gb[512 + hc]  + __ldcs(Gx + 512 + hc)  + bmih[512 + hc]  + bmhh[512 + hc]);
    float vg = tanhf(Ga[1024 + hc] + Gb[1024 + hc] + __ldcs(Gx + 1024 + hc) + bmih[1024 + hc] + bmhh[1024 + hc]);

    float fs = 0.0f;
#pragma unroll
    for (int j = 1; j <= KLAG; j++)
        fs = fmaf(g_wd[j - 1][hc], g_hist[(t - j) & (KLAG - 1)][idx], fs);

    float c1 = vi * vg - fs;
    g_hist[t & (KLAG - 1)][idx] = c1;
    float h1n = vo * tanhf(c1);
    split1(h1n, g_h1hi[idx], g_h1lo[idx]);
}

// --------------------- epilogue 2: LSTM cell + gather ------------------------
__global__ __launch_bounds__(256) void epi2_kernel(
    const float* __restrict__ bih, const float* __restrict__ bhh,
    const int* __restrict__ length, int t)
{
    cudaTriggerProgrammaticLaunchCompletion();
    cudaGridDependencySynchronize();

    const int idx = blockIdx.x * blockDim.x + threadIdx.x;
    const int b = idx >> 9, hc = idx & 511;
    const float* __restrict__ Ga = g_G2[0] + (size_t)b * N2;
    const float* __restrict__ Gb = g_G2[1] + (size_t)b * N2;

    float xi = sigf (Ga[hc]        + Gb[hc]        + bih[hc]        + bhh[hc]);
    float xf = sigf (Ga[512 + hc]  + Gb[512 + hc]  + bih[512 + hc]  + bhh[512 + hc]);
    float xg = tanhf(Ga[1024 + hc] + Gb[1024 + hc] + bih[1024 + hc] + bhh[1024 + hc]);
    float xo = sigf (Ga[1536 + hc] + Gb[1536 + hc] + bih[1536 + hc] + bhh[1536 + hc]);

    float cn = xf * g_c2[idx] + xi * xg;
    g_c2[idx] = cn;
    float hv = tanhf(xo * tanhf(cn));
    split1(hv, g_h2hi[idx], g_h2lo[idx]);
    if (length[b] == t) g_sel[idx] = hv;
}

// ------------------------------- head ---------------------------------------
__global__ __launch_bounds__(128) void head_kernel(
    const float* __restrict__ Wout, const float* __restrict__ bout,
    float* __restrict__ out)
{
    const int warp = (blockIdx.x * blockDim.x + threadIdx.x) >> 5;
    const int lane = threadIdx.x & 31;
    if (warp >= B_) return;

    float p[O_] = {0.f, 0.f, 0.f, 0.f, 0.f};
    for (int h = lane; h < H_; h += 32) {
        float s = g_sel[warp * H_ + h];
#pragma unroll
        for (int o = 0; o < O_; o++) p[o] = fmaf(s, Wout[o * H_ + h], p[o]);
    }
#pragma unroll
    for (int o = 0; o < O_; o++)
#pragma unroll
        for (int off = 16; off > 0; off >>= 1)
            p[o] += __shfl_xor_sync(0xffffffffu, p[o], off);

    if (lane == 0) {
        float l[O_], m = -1e30f;
#pragma unroll
        for (int o = 0; o < O_; o++) { l[o] = p[o] + bout[o]; m = fmaxf(m, l[o]); }
        float s = 0.0f;
#pragma unroll
        for (int o = 0; o < O_; o++) s += expf(l[o] - m);
        float ls = logf(s);
#pragma unroll
        for (int o = 0; o < O_; o++) out[warp * O_ + o] = l[o] - m - ls;
    }
}

// ----------------------------- launcher -------------------------------------
extern "C" void kernel_launch(void* const* d_in, const int* in_sizes, int n_in,
                              void* d_out, int out_size)
{
    const float* x    = (const float*)d_in[0];
    const int*   len  = (const int*)  d_in[1];
    const float* b_d  = (const float*)d_in[2];
    const float* Wmih = (const float*)d_in[3];
    const float* Wmhh = (const float*)d_in[4];
    const float* bmih = (const float*)d_in[5];
    const float* bmhh = (const float*)d_in[6];
    const float* Wih  = (const float*)d_in[7];
    const float* Whh  = (const float*)d_in[8];
    const float* bih  = (const float*)d_in[9];
    const float* bhh  = (const float*)d_in[10];
    const float* Wout = (const float*)d_in[11];
    const float* bout = (const float*)d_in[12];
    float* out = (float*)d_out;

    cudaFuncSetAttribute(gemmx_kernel,   cudaFuncAttributeMaxDynamicSharedMemorySize, SMEM_X);
    cudaFuncSetAttribute(gemm_kernel<1>, cudaFuncAttributeMaxDynamicSharedMemorySize, SMEM_S);
    cudaFuncSetAttribute(gemm_kernel<2>, cudaFuncAttributeMaxDynamicSharedMemorySize, SMEM_S);

    // PDL launch config (all step/epi kernels): programmatic stream serialization
    cudaLaunchAttribute pa;
    pa.id = cudaLaunchAttributeProgrammaticStreamSerialization;
    pa.val.programmaticStreamSerializationAllowed = 1;

    cudaLaunchConfig_t cfg_g1{}; cfg_g1.gridDim = dim3(N1 / 64, 4, 2);
    cfg_g1.blockDim = dim3(256); cfg_g1.dynamicSmemBytes = SMEM_S;
    cfg_g1.stream = 0; cfg_g1.attrs = &pa; cfg_g1.numAttrs = 1;

    cudaLaunchConfig_t cfg_g2{}; cfg_g2.gridDim = dim3(N2 / 64, 4, 2);
    cfg_g2.blockDim = dim3(256); cfg_g2.dynamicSmemBytes = SMEM_S;
    cfg_g2.stream = 0; cfg_g2.attrs = &pa; cfg_g2.numAttrs = 1;

    cudaLaunchConfig_t cfg_e{}; cfg_e.gridDim = dim3(BH / 256);
    cfg_e.blockDim = dim3(256); cfg_e.dynamicSmemBytes = 0;
    cfg_e.stream = 0; cfg_e.attrs = &pa; cfg_e.numAttrs = 1;

    init_kernel<<<1024, 256>>>(b_d, x, Wmih, Wmhh, Wih, Whh);

    // hoisted input projection over all timesteps (plain launch, full barrier)
    gemmx_kernel<<<dim3(N1 / 64, (T_ * B_) / 64), 256, SMEM_X>>>();

    for (int t = 0; t < T_; t++) {
        cudaLaunchKernelEx(&cfg_g1, gemm_kernel<1>, t);
        cudaLaunchKernelEx(&cfg_e,  epi1_kernel, bmih, bmhh, t);
        cudaLaunchKernelEx(&cfg_g2, gemm_kernel<2>, t);
        cudaLaunchKernelEx(&cfg_e,  epi2_kernel, bih, bhh, len, t);
    }

    head_kernel<<<64, 128>>>(Wout, bout, out);
}

// round 13
// speedup vs baseline: 1.4999x; 1.0147x over previous
#include <cuda_runtime.h>
#include <cuda_bf16.h>
#include <cstdint>

typedef uint32_t u32;
typedef uint64_t u64;
typedef unsigned short u16;

// ---------------------------------------------------------------------------
// MLSTMFixD round 13 = R7 step loop (proven, untouched) +
//  (a) gemmx rebuilt as throughput GEMM: 128x128 tile, warp 64x32
//      (MMA:LDSM=4), 3-stage cp.async w/ wait_group 1
//  (b) epi kernels vectorized float4 + precombined bias sums
// ---------------------------------------------------------------------------

constexpr int T_   = 128;
constexpr int B_   = 256;
constexpr int I_   = 512;
constexpr int H_   = 512;
constexpr int O_   = 5;
constexpr int KLAG = 32;
constexpr int BH   = B_ * H_;
constexpr int N1   = 3 * H_;   // 1536
constexpr int N2   = 4 * H_;   // 2048

constexpr int SMEM_X = 3 * 65536;   // gemmx: 3 stages x 64KB
constexpr int SMEM_S = 2 * 32768;   // step gemms: 2 stages x 32KB

// ------------------------- device scratch (static) -------------------------
__device__ __align__(16) u16 g_xhi[T_ * B_ * I_], g_xlo[T_ * B_ * I_];
__device__ __align__(16) u16 g_WxHi[N1 * 512],  g_WxLo[N1 * 512];    // Wmih
__device__ __align__(16) u16 g_W1Hi[N1 * 512],  g_W1Lo[N1 * 512];    // Wmhh
__device__ __align__(16) u16 g_W2Hi[N2 * 1024], g_W2Lo[N2 * 1024];   // [Wih|Whh]
__device__ __align__(16) u16 g_h1hi[BH], g_h1lo[BH];
__device__ __align__(16) u16 g_h2hi[BH], g_h2lo[BH];
__device__ float g_c2[BH];
__device__ float g_sel[BH];
__device__ float g_hist[KLAG][BH];          // circular by (t & 31)
__device__ float g_wd[KLAG][H_];
__device__ float g_bs1[N1];                 // bmih + bmhh
__device__ float g_bs2[N2];                 // bih + bhh
__device__ float g_XW[(size_t)T_ * B_ * N1];  // x @ Wmih^T for all t (streamed)
__device__ float g_G1[2][B_ * N1];          // K-split partials
__device__ float g_G2[2][B_ * N2];

// ------------------------------- helpers ------------------------------------
__device__ __forceinline__ u32 smem_u32(const void* p) {
    u32 a;
    asm("{ .reg .u64 t; cvta.to.shared.u64 t, %1; cvt.u32.u64 %0, t; }" : "=r"(a) : "l"(p));
    return a;
}
__device__ __forceinline__ void cpasync16(u32 dst, const void* src) {
    asm volatile("cp.async.cg.shared.global [%0], [%1], 16;" :: "r"(dst), "l"(src));
}
#define CP_COMMIT() asm volatile("cp.async.commit_group;" ::: "memory")
#define CP_WAIT0()  asm volatile("cp.async.wait_group 0;" ::: "memory")
#define CP_WAIT1()  asm volatile("cp.async.wait_group 1;" ::: "memory")

#define LDSM4(r, addr) asm volatile(                                           \
    "ldmatrix.sync.aligned.m8n8.x4.shared.b16 {%0,%1,%2,%3}, [%4];"            \
    : "=r"((r)[0]), "=r"((r)[1]), "=r"((r)[2]), "=r"((r)[3]) : "r"(addr))

#define MMA(d, a, b0, b1) asm volatile(                                        \
    "mma.sync.aligned.m16n8k16.row.col.f32.bf16.bf16.f32 "                     \
    "{%0,%1,%2,%3}, {%4,%5,%6,%7}, {%8,%9}, {%0,%1,%2,%3};"                    \
    : "+f"((d)[0]), "+f"((d)[1]), "+f"((d)[2]), "+f"((d)[3])                   \
    : "r"((a)[0]), "r"((a)[1]), "r"((a)[2]), "r"((a)[3]), "r"(b0), "r"(b1))

__device__ __forceinline__ u16 bf16bits(__nv_bfloat16 v) {
    __nv_bfloat16_raw r = *reinterpret_cast<__nv_bfloat16_raw*>(&v);
    return r.x;
}
__device__ __forceinline__ void split1(float a, u16& h, u16& l) {
    __nv_bfloat16 bh = __float2bfloat16_rn(a);
    float r = a - __bfloat162float(bh);
    __nv_bfloat16 bl = __float2bfloat16_rn(r);
    h = bf16bits(bh);
    l = bf16bits(bl);
}
__device__ __forceinline__ void split4(float4 v, u32& h01, u32& h23, u32& l01, u32& l23) {
    u16 h0, l0, h1, l1, h2, l2, h3, l3;
    split1(v.x, h0, l0); split1(v.y, h1, l1);
    split1(v.z, h2, l2); split1(v.w, h3, l3);
    h01 = (u32)h0 | ((u32)h1 << 16);  h23 = (u32)h2 | ((u32)h3 << 16);
    l01 = (u32)l0 | ((u32)l1 << 16);  l23 = (u32)l2 | ((u32)l3 << 16);
}
__device__ __forceinline__ float sigf(float x) { return 1.0f / (1.0f + expf(-x)); }
__device__ __forceinline__ float4 add4(float4 a, float4 b) {
    return make_float4(a.x + b.x, a.y + b.y, a.z + b.z, a.w + b.w);
}

// ------------------------------- init ---------------------------------------
__global__ __launch_bounds__(256) void init_kernel(
    const float* __restrict__ b_d,  const float* __restrict__ x,
    const float* __restrict__ Wmih, const float* __restrict__ Wmhh,
    const float* __restrict__ Wih,  const float* __restrict__ Whh,
    const float* __restrict__ bmih, const float* __restrict__ bmhh,
    const float* __restrict__ bih,  const float* __restrict__ bhh)
{
    const int tid = blockIdx.x * blockDim.x + threadIdx.x;
    const int tot = gridDim.x * blockDim.x;

    const int ngx = T_ * B_ * I_ / 4;
    for (int i = tid; i < ngx; i += tot) {
        float4 v = reinterpret_cast<const float4*>(x)[i];
        u32 h01, h23, l01, l23; split4(v, h01, h23, l01, l23);
        reinterpret_cast<uint2*>(g_xhi)[i] = make_uint2(h01, h23);
        reinterpret_cast<uint2*>(g_xlo)[i] = make_uint2(l01, l23);
    }

    const int ngWx = N1 * 512 / 4;
    for (int i = tid; i < ngWx; i += tot) {
        float4 v = reinterpret_cast<const float4*>(Wmih)[i];
        u32 h01, h23, l01, l23; split4(v, h01, h23, l01, l23);
        reinterpret_cast<uint2*>(g_WxHi)[i] = make_uint2(h01, h23);
        reinterpret_cast<uint2*>(g_WxLo)[i] = make_uint2(l01, l23);
    }
    for (int i = tid; i < ngWx; i += tot) {
        float4 v = reinterpret_cast<const float4*>(Wmhh)[i];
        u32 h01, h23, l01, l23; split4(v, h01, h23, l01, l23);
        reinterpret_cast<uint2*>(g_W1Hi)[i] = make_uint2(h01, h23);
        reinterpret_cast<uint2*>(g_W1Lo)[i] = make_uint2(l01, l23);
    }
    const int ngW2 = N2 * 1024 / 4;
    for (int i = tid; i < ngW2; i += tot) {
        int e = i * 4;
        int n = e >> 10, k = e & 1023;
        const float* src = (k < 512) ? (Wih + (size_t)n * 512 + k)
                                     : (Whh + (size_t)n * 512 + (k - 512));
        float4 v = *reinterpret_cast<const float4*>(src);
        u32 h01, h23, l01, l23; split4(v, h01, h23, l01, l23);
        reinterpret_cast<uint2*>(g_W2Hi)[i] = make_uint2(h01, h23);
        reinterpret_cast<uint2*>(g_W2Lo)[i] = make_uint2(l01, l23);
    }

    for (int i = tid; i < N1; i += tot) g_bs1[i] = bmih[i] + bmhh[i];
    for (int i = tid; i < N2; i += tot) g_bs2[i] = bih[i] + bhh[i];

    float4 z4 = make_float4(0.f, 0.f, 0.f, 0.f);
    for (int i = tid; i < KLAG * BH / 4; i += tot)
        reinterpret_cast<float4*>(&g_hist[0][0])[i] = z4;
    for (int i = tid; i < BH / 4; i += tot) {
        reinterpret_cast<float4*>(g_c2)[i]  = z4;
        reinterpret_cast<float4*>(g_sel)[i] = z4;
        reinterpret_cast<uint2*>(g_h1hi)[i] = make_uint2(0u, 0u);
        reinterpret_cast<uint2*>(g_h1lo)[i] = make_uint2(0u, 0u);
        reinterpret_cast<uint2*>(g_h2hi)[i] = make_uint2(0u, 0u);
        reinterpret_cast<uint2*>(g_h2lo)[i] = make_uint2(0u, 0u);
    }

    if (tid < H_) {
        float d = 0.5f * (1.0f / (1.0f + expf(-b_d[tid])));
        float c = 1.0f;
        for (int j = 1; j <= KLAG; j++) {
            c *= ((float)(j - 1) - d) / (float)j;
            g_wd[j - 1][tid] = c;
        }
    }
}

// ------------------- XW precompute: XW = x @ Wmih^T --------------------------
// Throughput GEMM: CTA 128x128, 256 thr, 8 warps (2m x 4n, warp 64x32),
// K=512 in 8 chunks, 3-stage cp.async (wait_group 1), streaming stores.
// grid (12, 256) = 3072 CTAs.
__global__ __launch_bounds__(256, 1) void gemmx_kernel()
{
    extern __shared__ __align__(128) char smem[];
    const u32 sb  = smem_u32(smem);
    const int tid = threadIdx.x;
    const int wid = tid >> 5, lane = tid & 31;
    const int bn  = blockIdx.x * 128;
    const int bm  = blockIdx.y * 128;

    // loader: 4096 16B units per stage (Ahi|Alo|Bhi|Blo, 16KB each), 16/thread
    auto load_chunk = [&](int c, int stage) {
        const int k0 = c * 64;
        const u32 base = sb + stage * 65536;
#pragma unroll
        for (int it = 0; it < 4; it++) {
            const int u = tid + it * 256;            // 0..1023
            const int r = u >> 3, cu = u & 7;
            const u32 so = (u32)(r * 128 + ((cu ^ (r & 7)) << 4));
            const size_t ao = (size_t)(bm + r) * 512 + k0 + cu * 8;
            const size_t bo = (size_t)(bn + r) * 512 + k0 + cu * 8;
            cpasync16(base + so,         g_xhi  + ao);
            cpasync16(base + 16384 + so, g_xlo  + ao);
            cpasync16(base + 32768 + so, g_WxHi + bo);
            cpasync16(base + 49152 + so, g_WxLo + bo);
        }
    };

    const int warp_m = wid & 1;        // 2 tiles of 64
    const int warp_n = wid >> 1;       // 4 tiles of 32
    const int arow0  = warp_m * 64 + (lane & 15);
    const int akh    = lane >> 4;
    const int asw    = arow0 & 7;      // +16k doesn't change &7
    const int brow0  = warp_n * 32 + (lane & 7) + ((lane >> 4) << 3);
    const int bkh    = (lane >> 3) & 1;
    const int bsw    = brow0 & 7;

    float acc[4][4][4] = {};           // [m-frag][n8][4]

    load_chunk(0, 0); CP_COMMIT();
    load_chunk(1, 1); CP_COMMIT();

    for (int c = 0; c < 8; c++) {
        if (c + 1 < 8) { CP_WAIT1(); } else { CP_WAIT0(); }
        __syncthreads();
        if (c + 2 < 8) { load_chunk(c + 2, (c + 2) % 3); CP_COMMIT(); }

        const u32 Ah = sb + (c % 3) * 65536;
        const u32 Al = Ah + 16384;
        const u32 Bh = Ah + 32768;
        const u32 Bl = Ah + 49152;

#pragma unroll
        for (int kk = 0; kk < 4; kk++) {
            const u32 sa  = (((u32)(kk * 2 + akh) ^ (u32)asw) << 4);
            const u32 sbo = (((u32)(kk * 2 + bkh) ^ (u32)bsw) << 4);

            u32 ah[4][4], al[4][4], bh[2][4], bl[2][4];
#pragma unroll
            for (int mf = 0; mf < 4; mf++) {
                const u32 ro = (u32)((arow0 + mf * 16) * 128);
                LDSM4(ah[mf], Ah + ro + sa);
                LDSM4(al[mf], Al + ro + sa);
            }
#pragma unroll
            for (int bf = 0; bf < 2; bf++) {
                const u32 ro = (u32)((brow0 + bf * 16) * 128);
                LDSM4(bh[bf], Bh + ro + sbo);
                LDSM4(bl[bf], Bl + ro + sbo);
            }
#pragma unroll
            for (int mf = 0; mf < 4; mf++)
#pragma unroll
                for (int bf = 0; bf < 2; bf++)
#pragma unroll
                    for (int n8 = 0; n8 < 2; n8++) {
                        float* d = acc[mf][bf * 2 + n8];
                        MMA(d, ah[mf], bh[bf][2 * n8], bh[bf][2 * n8 + 1]);
                        MMA(d, ah[mf], bl[bf][2 * n8], bl[bf][2 * n8 + 1]);
                        MMA(d, al[mf], bh[bf][2 * n8], bh[bf][2 * n8 + 1]);
                    }
        }
    }

#pragma unroll
    for (int mf = 0; mf < 4; mf++)
#pragma unroll
        for (int j = 0; j < 4; j++) {
            const int gm = bm + warp_m * 64 + mf * 16 + (lane >> 2);
            const int gn = bn + warp_n * 32 + j * 8 + 2 * (lane & 3);
            __stcs(reinterpret_cast<float2*>(&g_XW[(size_t)gm * N1 + gn]),
                   make_float2(acc[mf][j][0], acc[mf][j][1]));
            __stcs(reinterpret_cast<float2*>(&g_XW[(size_t)(gm + 8) * N1 + gn]),
                   make_float2(acc[mf][j][2], acc[mf][j][3]));
        }
}

// ----------------------- step GEMMs (R7, untouched) --------------------------
// SET=1: G1[kz][256,1536] = h1 @ Wmhh^T      grid (24, 4, 2)  K=256/CTA, 4 chunks
// SET=2: G2[kz][256,2048] = [h1n|h2] @ W2^T  grid (32, 4, 2)  K=512/CTA, 8 chunks
template <int SET>
__global__ __launch_bounds__(256, 2) void gemm_kernel(int t)
{
    constexpr int NC  = (SET == 1) ? 4 : 8;
    constexpr int ldB = (SET == 2) ? 1024 : 512;
    constexpr int ldG = (SET == 2) ? N2 : N1;

    extern __shared__ __align__(128) char smem[];
    const u32 sb  = smem_u32(smem);
    const int tid = threadIdx.x;
    const int wid = tid >> 5, lane = tid & 31;
    const int bn  = blockIdx.x * 64;
    const int bm  = blockIdx.y * 64;
    const int kz  = blockIdx.z;
    const int kbase = (SET == 1) ? kz * 256 : kz * 512;

    const u16* __restrict__ BHi = (SET == 1) ? g_W1Hi : g_W2Hi;
    const u16* __restrict__ BLo = (SET == 1) ? g_W1Lo : g_W2Lo;
    float* __restrict__ G = (SET == 1) ? g_G1[kz] : g_G2[kz];

    const int lr  = tid >> 3;
    const int lcu = tid & 7;
    auto load_chunk = [&](int c, int stage) {
        const int k0 = kbase + c * 64;
        const u16* ah; const u16* al; int kloc;
        if (SET == 2 && k0 >= 512) { ah = g_h2hi; al = g_h2lo; kloc = k0 - 512; }
        else                       { ah = g_h1hi; al = g_h1lo; kloc = k0;       }
        const u32 base = sb + stage * 32768;
#pragma unroll
        for (int j = 0; j < 2; j++) {
            const int r = lr + j * 32;
            const u32 so = (u32)(r * 128 + ((lcu ^ (r & 7)) << 4));
            const size_t ao = (size_t)(bm + r) * 512 + kloc + lcu * 8;
            const size_t bo = (size_t)(bn + r) * ldB + k0 + lcu * 8;
            cpasync16(base + so,         ah  + ao);
            cpasync16(base + 8192 + so,  al  + ao);
            cpasync16(base + 16384 + so, BHi + bo);
            cpasync16(base + 24576 + so, BLo + bo);
        }
    };

    const int warp_m = wid & 1;
    const int warp_n = wid >> 1;
    const int arow   = warp_m * 32 + (lane & 15);
    const int akh    = lane >> 4;
    const int asw    = arow & 7;
    const u32 aoff0  = (u32)(arow * 128);
    const u32 aoff1  = (u32)((arow + 16) * 128);
    const int brow   = warp_n * 16 + (lane & 7) + ((lane >> 4) << 3);
    const int bkh    = (lane >> 3) & 1;
    const int bsw    = brow & 7;
    const u32 boff   = (u32)(brow * 128);

    float acc[2][2][4] = {};

    load_chunk(0, 0); CP_COMMIT();
    for (int c = 0; c < NC; c++) {
        CP_WAIT0();
        __syncthreads();
        if (c + 1 < NC) { load_chunk(c + 1, (c + 1) & 1); CP_COMMIT(); }

        const u32 Ah = sb + (c & 1) * 32768;
        const u32 Al = Ah + 8192;
        const u32 Bh = Ah + 16384;
        const u32 Bl = Ah + 24576;
#pragma unroll
        for (int kk = 0; kk < 4; kk++) {
            const u32 sa  = (((u32)(kk * 2 + akh) ^ (u32)asw) << 4);
            const u32 sbo = (((u32)(kk * 2 + bkh) ^ (u32)bsw) << 4);
            u32 ah0[4], ah1[4], al0[4], al1[4], bh[4], bl[4];
            LDSM4(ah0, Ah + aoff0 + sa);
            LDSM4(ah1, Ah + aoff1 + sa);
            LDSM4(al0, Al + aoff0 + sa);
            LDSM4(al1, Al + aoff1 + sa);
            LDSM4(bh,  Bh + boff + sbo);
            LDSM4(bl,  Bl + boff + sbo);
#pragma unroll
            for (int nt = 0; nt < 2; nt++) {
                MMA(acc[0][nt], ah0, bh[2 * nt], bh[2 * nt + 1]);
                MMA(acc[1][nt], ah1, bh[2 * nt], bh[2 * nt + 1]);
                MMA(acc[0][nt], ah0, bl[2 * nt], bl[2 * nt + 1]);
                MMA(acc[1][nt], ah1, bl[2 * nt], bl[2 * nt + 1]);
                MMA(acc[0][nt], al0, bh[2 * nt], bh[2 * nt + 1]);
                MMA(acc[1][nt], al1, bh[2 * nt], bh[2 * nt + 1]);
            }
        }
    }

#pragma unroll
    for (int mt = 0; mt < 2; mt++)
#pragma unroll
        for (int nt = 0; nt < 2; nt++) {
            const int gm = bm + warp_m * 32 + mt * 16 + (lane >> 2);
            const int gn = bn + warp_n * 16 + nt * 8 + 2 * (lane & 3);
            *reinterpret_cast<float2*>(&G[(size_t)gm * ldG + gn]) =
                make_float2(acc[mt][nt][0], acc[mt][nt][1]);
            *reinterpret_cast<float2*>(&G[(size_t)(gm + 8) * ldG + gn]) =
                make_float2(acc[mt][nt][2], acc[mt][nt][3]);
        }
}

// --------------- epilogue 1 (float4): mLSTM gates + frac filter --------------
// grid 128 x 256: one float4 (4 h-cols) per thread.
__global__ __launch_bounds__(256) void epi1_kernel(int t)
{
    const int g  = blockIdx.x * blockDim.x + threadIdx.x;   // 0..BH/4-1
    const int b  = g >> 7;
    const int hc = (g & 127) << 2;
    const int idx = b * 512 + hc;
    const float* __restrict__ Pa = g_G1[0] + (size_t)b * N1;
    const float* __restrict__ Pb = g_G1[1] + (size_t)b * N1;
    const float* __restrict__ Gx = g_XW + ((size_t)t * B_ + b) * N1;

    float4 gi = add4(add4(*(const float4*)(Pa + hc),        *(const float4*)(Pb + hc)),
                     add4(__ldcs((const float4*)(Gx + hc)),        *(const float4*)(g_bs1 + hc)));
    float4 go = add4(add4(*(const float4*)(Pa + 512 + hc),  *(const float4*)(Pb + 512 + hc)),
                     add4(__ldcs((const float4*)(Gx + 512 + hc)),  *(const float4*)(g_bs1 + 512 + hc)));
    float4 gg = add4(add4(*(const float4*)(Pa + 1024 + hc), *(const float4*)(Pb + 1024 + hc)),
                     add4(__ldcs((const float4*)(Gx + 1024 + hc)), *(const float4*)(g_bs1 + 1024 + hc)));

    float4 fs = make_float4(0.f, 0.f, 0.f, 0.f);
#pragma unroll
    for (int j = 1; j <= KLAG; j++) {
        const float4 hv = *(const float4*)(&g_hist[(t - j) & (KLAG - 1)][idx]);
        const float4 wv = *(const float4*)(&g_wd[j - 1][hc]);
        fs.x = fmaf(wv.x, hv.x, fs.x);
        fs.y = fmaf(wv.y, hv.y, fs.y);
        fs.z = fmaf(wv.z, hv.z, fs.z);
        fs.w = fmaf(wv.w, hv.w, fs.w);
    }

    float4 c1;
    c1.x = sigf(gi.x) * tanhf(gg.x) - fs.x;
    c1.y = sigf(gi.y) * tanhf(gg.y) - fs.y;
    c1.z = sigf(gi.z) * tanhf(gg.z) - fs.z;
    c1.w = sigf(gi.w) * tanhf(gg.w) - fs.w;
    *(float4*)(&g_hist[t & (KLAG - 1)][idx]) = c1;

    float4 h1n;
    h1n.x = sigf(go.x) * tanhf(c1.x);
    h1n.y = sigf(go.y) * tanhf(c1.y);
    h1n.z = sigf(go.z) * tanhf(c1.z);
    h1n.w = sigf(go.w) * tanhf(c1.w);

    u32 h01, h23, l01, l23;
    split4(h1n, h01, h23, l01, l23);
    *reinterpret_cast<uint2*>(&g_h1hi[idx]) = make_uint2(h01, h23);
    *reinterpret_cast<uint2*>(&g_h1lo[idx]) = make_uint2(l01, l23);
}

// --------------- epilogue 2 (float4): LSTM cell + gather ---------------------
__global__ __launch_bounds__(256) void epi2_kernel(const int* __restrict__ length, int t)
{
    const int g  = blockIdx.x * blockDim.x + threadIdx.x;
    const int b  = g >> 7;
    const int hc = (g & 127) << 2;
    const int idx = b * 512 + hc;
    const float* __restrict__ Pa = g_G2[0] + (size_t)b * N2;
    const float* __restrict__ Pb = g_G2[1] + (size_t)b * N2;

    float4 gi = add4(add4(*(const float4*)(Pa + hc),        *(const float4*)(Pb + hc)),
                     *(const float4*)(g_bs2 + hc));
    float4 gf = add4(add4(*(const float4*)(Pa + 512 + hc),  *(const float4*)(Pb + 512 + hc)),
                     *(const float4*)(g_bs2 + 512 + hc));
    float4 gg = add4(add4(*(const float4*)(Pa + 1024 + hc), *(const float4*)(Pb + 1024 + hc)),
                     *(const float4*)(g_bs2 + 1024 + hc));
    float4 go = add4(add4(*(const float4*)(Pa + 1536 + hc), *(const float4*)(Pb + 1536 + hc)),
                     *(const float4*)(g_bs2 + 1536 + hc));

    float4 cp = *(const float4*)(&g_c2[idx]);
    float4 cn, hv;
    cn.x = sigf(gf.x) * cp.x + sigf(gi.x) * tanhf(gg.x);
    cn.y = sigf(gf.y) * cp.y + sigf(gi.y) * tanhf(gg.y);
    cn.z = sigf(gf.z) * cp.z + sigf(gi.z) * tanhf(gg.z);
    cn.w = sigf(gf.w) * cp.w + sigf(gi.w) * tanhf(gg.w);
    *(float4*)(&g_c2[idx]) = cn;

    hv.x = tanhf(sigf(go.x) * tanhf(cn.x));
    hv.y = tanhf(sigf(go.y) * tanhf(cn.y));
    hv.z = tanhf(sigf(go.z) * tanhf(cn.z));
    hv.w = tanhf(sigf(go.w) * tanhf(cn.w));

    u32 h01, h23, l01, l23;
    split4(hv, h01, h23, l01, l23);
    *reinterpret_cast<uint2*>(&g_h2hi[idx]) = make_uint2(h01, h23);
    *reinterpret_cast<uint2*>(&g_h2lo[idx]) = make_uint2(l01, l23);
    if (length[b] == t) *(float4*)(&g_sel[idx]) = hv;
}

// ------------------------------- head ---------------------------------------
__global__ __launch_bounds__(128) void head_kernel(
    const float* __restrict__ Wout, const float* __restrict__ bout,
    float* __restrict__ out)
{
    const int warp = (blockIdx.x * blockDim.x + threadIdx.x) >> 5;
    const int lane = threadIdx.x & 31;
    if (warp >= B_) return;

    float p[O_] = {0.f, 0.f, 0.f, 0.f, 0.f};
    for (int h = lane; h < H_; h += 32) {
        float s = g_sel[warp * H_ + h];
#pragma unroll
        for (int o = 0; o < O_; o++) p[o] = fmaf(s, Wout[o * H_ + h], p[o]);
    }
#pragma unroll
    for (int o = 0; o < O_; o++)
#pragma unroll
        for (int off = 16; off > 0; off >>= 1)
            p[o] += __shfl_xor_sync(0xffffffffu, p[o], off);

    if (lane == 0) {
        float l[O_], m = -1e30f;
#pragma unroll
        for (int o = 0; o < O_; o++) { l[o] = p[o] + bout[o]; m = fmaxf(m, l[o]); }
        float s = 0.0f;
#pragma unroll
        for (int o = 0; o < O_; o++) s += expf(l[o] - m);
        float ls = logf(s);
#pragma unroll
        for (int o = 0; o < O_; o++) out[warp * O_ + o] = l[o] - m - ls;
    }
}

// ----------------------------- launcher -------------------------------------
extern "C" void kernel_launch(void* const* d_in, const int* in_sizes, int n_in,
                              void* d_out, int out_size)
{
    const float* x    = (const float*)d_in[0];
    const int*   len  = (const int*)  d_in[1];
    const float* b_d  = (const float*)d_in[2];
    const float* Wmih = (const float*)d_in[3];
    const float* Wmhh = (const float*)d_in[4];
    const float* bmih = (const float*)d_in[5];
    const float* bmhh = (const float*)d_in[6];
    const float* Wih  = (const float*)d_in[7];
    const float* Whh  = (const float*)d_in[8];
    const float* bih  = (const float*)d_in[9];
    const float* bhh  = (const float*)d_in[10];
    const float* Wout = (const float*)d_in[11];
    const float* bout = (const float*)d_in[12];
    float* out = (float*)d_out;

    cudaFuncSetAttribute(gemmx_kernel,   cudaFuncAttributeMaxDynamicSharedMemorySize, SMEM_X);
    cudaFuncSetAttribute(gemm_kernel<1>, cudaFuncAttributeMaxDynamicSharedMemorySize, SMEM_S);
    cudaFuncSetAttribute(gemm_kernel<2>, cudaFuncAttributeMaxDynamicSharedMemorySize, SMEM_S);

    init_kernel<<<1024, 256>>>(b_d, x, Wmih, Wmhh, Wih, Whh, bmih, bmhh, bih, bhh);

    // hoisted input projection over all timesteps (throughput GEMM)
    gemmx_kernel<<<dim3(N1 / 128, (T_ * B_) / 128), 256, SMEM_X>>>();

    for (int t = 0; t < T_; t++) {
        gemm_kernel<1><<<dim3(N1 / 64, 4, 2), 256, SMEM_S>>>(t);
        epi1_kernel<<<BH / 1024, 256>>>(t);
        gemm_kernel<2><<<dim3(N2 / 64, 4, 2), 256, SMEM_S>>>(t);
        epi2_kernel<<<BH / 1024, 256>>>(len, t);
    }

    head_kernel<<<64, 128>>>(Wout, bout, out);
}

// round 14
// speedup vs baseline: 1.7245x; 1.1498x over previous
#include <cuda_runtime.h>
#include <cuda_bf16.h>
#include <cstdint>

typedef uint32_t u32;
typedef uint64_t u64;
typedef unsigned short u16;

// ---------------------------------------------------------------------------
// MLSTMFixD round 14 = R7 components (proven) + concurrency restructure:
//  - loop order g2(t), g1(t+1), eX(t) where eX = epi2(t) ∥ epi1(t+1) fused
//    into ONE 1024-CTA launch (bodies verbatim R7 scalar, zero numeric change)
//  - gemmx = R13 throughput rebuild (128x128 tile, 3-stage) — kept
// ---------------------------------------------------------------------------

constexpr int T_   = 128;
constexpr int B_   = 256;
constexpr int I_   = 512;
constexpr int H_   = 512;
constexpr int O_   = 5;
constexpr int KLAG = 32;
constexpr int BH   = B_ * H_;
constexpr int N1   = 3 * H_;   // 1536
constexpr int N2   = 4 * H_;   // 2048

constexpr int SMEM_X = 3 * 65536;   // gemmx: 3 stages x 64KB
constexpr int SMEM_S = 2 * 32768;   // step gemms: 2 stages x 32KB

// ------------------------- device scratch (static) -------------------------
__device__ __align__(16) u16 g_xhi[T_ * B_ * I_], g_xlo[T_ * B_ * I_];
__device__ __align__(16) u16 g_WxHi[N1 * 512],  g_WxLo[N1 * 512];    // Wmih
__device__ __align__(16) u16 g_W1Hi[N1 * 512],  g_W1Lo[N1 * 512];    // Wmhh
__device__ __align__(16) u16 g_W2Hi[N2 * 1024], g_W2Lo[N2 * 1024];   // [Wih|Whh]
__device__ __align__(16) u16 g_h1hi[BH], g_h1lo[BH];
__device__ __align__(16) u16 g_h2hi[BH], g_h2lo[BH];
__device__ float g_c2[BH];
__device__ float g_sel[BH];
__device__ float g_hist[KLAG][BH];          // circular by (t & 31)
__device__ float g_wd[KLAG][H_];
__device__ float g_XW[(size_t)T_ * B_ * N1];  // x @ Wmih^T for all t (streamed)
__device__ float g_G1[2][B_ * N1];          // K-split partials
__device__ float g_G2[2][B_ * N2];

// ------------------------------- helpers ------------------------------------
__device__ __forceinline__ u32 smem_u32(const void* p) {
    u32 a;
    asm("{ .reg .u64 t; cvta.to.shared.u64 t, %1; cvt.u32.u64 %0, t; }" : "=r"(a) : "l"(p));
    return a;
}
__device__ __forceinline__ void cpasync16(u32 dst, const void* src) {
    asm volatile("cp.async.cg.shared.global [%0], [%1], 16;" :: "r"(dst), "l"(src));
}
#define CP_COMMIT() asm volatile("cp.async.commit_group;" ::: "memory")
#define CP_WAIT0()  asm volatile("cp.async.wait_group 0;" ::: "memory")
#define CP_WAIT1()  asm volatile("cp.async.wait_group 1;" ::: "memory")

#define LDSM4(r, addr) asm volatile(                                           \
    "ldmatrix.sync.aligned.m8n8.x4.shared.b16 {%0,%1,%2,%3}, [%4];"            \
    : "=r"((r)[0]), "=r"((r)[1]), "=r"((r)[2]), "=r"((r)[3]) : "r"(addr))

#define MMA(d, a, b0, b1) asm volatile(                                        \
    "mma.sync.aligned.m16n8k16.row.col.f32.bf16.bf16.f32 "                     \
    "{%0,%1,%2,%3}, {%4,%5,%6,%7}, {%8,%9}, {%0,%1,%2,%3};"                    \
    : "+f"((d)[0]), "+f"((d)[1]), "+f"((d)[2]), "+f"((d)[3])                   \
    : "r"((a)[0]), "r"((a)[1]), "r"((a)[2]), "r"((a)[3]), "r"(b0), "r"(b1))

__device__ __forceinline__ u16 bf16bits(__nv_bfloat16 v) {
    __nv_bfloat16_raw r = *reinterpret_cast<__nv_bfloat16_raw*>(&v);
    return r.x;
}
__device__ __forceinline__ void split1(float a, u16& h, u16& l) {
    __nv_bfloat16 bh = __float2bfloat16_rn(a);
    float r = a - __bfloat162float(bh);
    __nv_bfloat16 bl = __float2bfloat16_rn(r);
    h = bf16bits(bh);
    l = bf16bits(bl);
}
__device__ __forceinline__ void split4(float4 v, u32& h01, u32& h23, u32& l01, u32& l23) {
    u16 h0, l0, h1, l1, h2, l2, h3, l3;
    split1(v.x, h0, l0); split1(v.y, h1, l1);
    split1(v.z, h2, l2); split1(v.w, h3, l3);
    h01 = (u32)h0 | ((u32)h1 << 16);  h23 = (u32)h2 | ((u32)h3 << 16);
    l01 = (u32)l0 | ((u32)l1 << 16);  l23 = (u32)l2 | ((u32)l3 << 16);
}
__device__ __forceinline__ float sigf(float x) { return 1.0f / (1.0f + expf(-x)); }

// ------------------------------- init ---------------------------------------
__global__ __launch_bounds__(256) void init_kernel(
    const float* __restrict__ b_d,  const float* __restrict__ x,
    const float* __restrict__ Wmih, const float* __restrict__ Wmhh,
    const float* __restrict__ Wih,  const float* __restrict__ Whh)
{
    const int tid = blockIdx.x * blockDim.x + threadIdx.x;
    const int tot = gridDim.x * blockDim.x;

    const int ngx = T_ * B_ * I_ / 4;
    for (int i = tid; i < ngx; i += tot) {
        float4 v = reinterpret_cast<const float4*>(x)[i];
        u32 h01, h23, l01, l23; split4(v, h01, h23, l01, l23);
        reinterpret_cast<uint2*>(g_xhi)[i] = make_uint2(h01, h23);
        reinterpret_cast<uint2*>(g_xlo)[i] = make_uint2(l01, l23);
    }

    const int ngWx = N1 * 512 / 4;
    for (int i = tid; i < ngWx; i += tot) {
        float4 v = reinterpret_cast<const float4*>(Wmih)[i];
        u32 h01, h23, l01, l23; split4(v, h01, h23, l01, l23);
        reinterpret_cast<uint2*>(g_WxHi)[i] = make_uint2(h01, h23);
        reinterpret_cast<uint2*>(g_WxLo)[i] = make_uint2(l01, l23);
    }
    for (int i = tid; i < ngWx; i += tot) {
        float4 v = reinterpret_cast<const float4*>(Wmhh)[i];
        u32 h01, h23, l01, l23; split4(v, h01, h23, l01, l23);
        reinterpret_cast<uint2*>(g_W1Hi)[i] = make_uint2(h01, h23);
        reinterpret_cast<uint2*>(g_W1Lo)[i] = make_uint2(l01, l23);
    }
    const int ngW2 = N2 * 1024 / 4;
    for (int i = tid; i < ngW2; i += tot) {
        int e = i * 4;
        int n = e >> 10, k = e & 1023;
        const float* src = (k < 512) ? (Wih + (size_t)n * 512 + k)
                                     : (Whh + (size_t)n * 512 + (k - 512));
        float4 v = *reinterpret_cast<const float4*>(src);
        u32 h01, h23, l01, l23; split4(v, h01, h23, l01, l23);
        reinterpret_cast<uint2*>(g_W2Hi)[i] = make_uint2(h01, h23);
        reinterpret_cast<uint2*>(g_W2Lo)[i] = make_uint2(l01, l23);
    }

    float4 z4 = make_float4(0.f, 0.f, 0.f, 0.f);
    for (int i = tid; i < KLAG * BH / 4; i += tot)
        reinterpret_cast<float4*>(&g_hist[0][0])[i] = z4;
    for (int i = tid; i < BH / 4; i += tot) {
        reinterpret_cast<float4*>(g_c2)[i]  = z4;
        reinterpret_cast<float4*>(g_sel)[i] = z4;
        reinterpret_cast<uint2*>(g_h1hi)[i] = make_uint2(0u, 0u);
        reinterpret_cast<uint2*>(g_h1lo)[i] = make_uint2(0u, 0u);
        reinterpret_cast<uint2*>(g_h2hi)[i] = make_uint2(0u, 0u);
        reinterpret_cast<uint2*>(g_h2lo)[i] = make_uint2(0u, 0u);
    }

    if (tid < H_) {
        float d = 0.5f * (1.0f / (1.0f + expf(-b_d[tid])));
        float c = 1.0f;
        for (int j = 1; j <= KLAG; j++) {
            c *= ((float)(j - 1) - d) / (float)j;
            g_wd[j - 1][tid] = c;
        }
    }
}

// ------------------- XW precompute (R13 throughput GEMM) ---------------------
// CTA 128x128, 256 thr, 8 warps (2m x 4n, warp 64x32), 3-stage cp.async.
__global__ __launch_bounds__(256, 1) void gemmx_kernel()
{
    extern __shared__ __align__(128) char smem[];
    const u32 sb  = smem_u32(smem);
    const int tid = threadIdx.x;
    const int wid = tid >> 5, lane = tid & 31;
    const int bn  = blockIdx.x * 128;
    const int bm  = blockIdx.y * 128;

    auto load_chunk = [&](int c, int stage) {
        const int k0 = c * 64;
        const u32 base = sb + stage * 65536;
#pragma unroll
        for (int it = 0; it < 4; it++) {
            const int u = tid + it * 256;
            const int r = u >> 3, cu = u & 7;
            const u32 so = (u32)(r * 128 + ((cu ^ (r & 7)) << 4));
            const size_t ao = (size_t)(bm + r) * 512 + k0 + cu * 8;
            const size_t bo = (size_t)(bn + r) * 512 + k0 + cu * 8;
            cpasync16(base + so,         g_xhi  + ao);
            cpasync16(base + 16384 + so, g_xlo  + ao);
            cpasync16(base + 32768 + so, g_WxHi + bo);
            cpasync16(base + 49152 + so, g_WxLo + bo);
        }
    };

    const int warp_m = wid & 1;
    const int warp_n = wid >> 1;
    const int arow0  = warp_m * 64 + (lane & 15);
    const int akh    = lane >> 4;
    const int asw    = arow0 & 7;
    const int brow0  = warp_n * 32 + (lane & 7) + ((lane >> 4) << 3);
    const int bkh    = (lane >> 3) & 1;
    const int bsw    = brow0 & 7;

    float acc[4][4][4] = {};

    load_chunk(0, 0); CP_COMMIT();
    load_chunk(1, 1); CP_COMMIT();

    for (int c = 0; c < 8; c++) {
        if (c + 1 < 8) { CP_WAIT1(); } else { CP_WAIT0(); }
        __syncthreads();
        if (c + 2 < 8) { load_chunk(c + 2, (c + 2) % 3); CP_COMMIT(); }

        const u32 Ah = sb + (c % 3) * 65536;
        const u32 Al = Ah + 16384;
        const u32 Bh = Ah + 32768;
        const u32 Bl = Ah + 49152;

#pragma unroll
        for (int kk = 0; kk < 4; kk++) {
            const u32 sa  = (((u32)(kk * 2 + akh) ^ (u32)asw) << 4);
            const u32 sbo = (((u32)(kk * 2 + bkh) ^ (u32)bsw) << 4);

            u32 ah[4][4], al[4][4], bh[2][4], bl[2][4];
#pragma unroll
            for (int mf = 0; mf < 4; mf++) {
                const u32 ro = (u32)((arow0 + mf * 16) * 128);
                LDSM4(ah[mf], Ah + ro + sa);
                LDSM4(al[mf], Al + ro + sa);
            }
#pragma unroll
            for (int bf = 0; bf < 2; bf++) {
                const u32 ro = (u32)((brow0 + bf * 16) * 128);
                LDSM4(bh[bf], Bh + ro + sbo);
                LDSM4(bl[bf], Bl + ro + sbo);
            }
#pragma unroll
            for (int mf = 0; mf < 4; mf++)
#pragma unroll
                for (int bf = 0; bf < 2; bf++)
#pragma unroll
                    for (int n8 = 0; n8 < 2; n8++) {
                        float* d = acc[mf][bf * 2 + n8];
                        MMA(d, ah[mf], bh[bf][2 * n8], bh[bf][2 * n8 + 1]);
                        MMA(d, ah[mf], bl[bf][2 * n8], bl[bf][2 * n8 + 1]);
                        MMA(d, al[mf], bh[bf][2 * n8], bh[bf][2 * n8 + 1]);
                    }
        }
    }

#pragma unroll
    for (int mf = 0; mf < 4; mf++)
#pragma unroll
        for (int j = 0; j < 4; j++) {
            const int gm = bm + warp_m * 64 + mf * 16 + (lane >> 2);
            const int gn = bn + warp_n * 32 + j * 8 + 2 * (lane & 3);
            __stcs(reinterpret_cast<float2*>(&g_XW[(size_t)gm * N1 + gn]),
                   make_float2(acc[mf][j][0], acc[mf][j][1]));
            __stcs(reinterpret_cast<float2*>(&g_XW[(size_t)(gm + 8) * N1 + gn]),
                   make_float2(acc[mf][j][2], acc[mf][j][3]));
        }
}

// ----------------------- step GEMMs (R7, untouched) --------------------------
template <int SET>
__global__ __launch_bounds__(256, 2) void gemm_kernel(int t)
{
    constexpr int NC  = (SET == 1) ? 4 : 8;
    constexpr int ldB = (SET == 2) ? 1024 : 512;
    constexpr int ldG = (SET == 2) ? N2 : N1;

    extern __shared__ __align__(128) char smem[];
    const u32 sb  = smem_u32(smem);
    const int tid = threadIdx.x;
    const int wid = tid >> 5, lane = tid & 31;
    const int bn  = blockIdx.x * 64;
    const int bm  = blockIdx.y * 64;
    const int kz  = blockIdx.z;
    const int kbase = (SET == 1) ? kz * 256 : kz * 512;

    const u16* __restrict__ BHi = (SET == 1) ? g_W1Hi : g_W2Hi;
    const u16* __restrict__ BLo = (SET == 1) ? g_W1Lo : g_W2Lo;
    float* __restrict__ G = (SET == 1) ? g_G1[kz] : g_G2[kz];

    const int lr  = tid >> 3;
    const int lcu = tid & 7;
    auto load_chunk = [&](int c, int stage) {
        const int k0 = kbase + c * 64;
        const u16* ah; const u16* al; int kloc;
        if (SET == 2 && k0 >= 512) { ah = g_h2hi; al = g_h2lo; kloc = k0 - 512; }
        else                       { ah = g_h1hi; al = g_h1lo; kloc = k0;       }
        const u32 base = sb + stage * 32768;
#pragma unroll
        for (int j = 0; j < 2; j++) {
            const int r = lr + j * 32;
            const u32 so = (u32)(r * 128 + ((lcu ^ (r & 7)) << 4));
            const size_t ao = (size_t)(bm + r) * 512 + kloc + lcu * 8;
            const size_t bo = (size_t)(bn + r) * ldB + k0 + lcu * 8;
            cpasync16(base + so,         ah  + ao);
            cpasync16(base + 8192 + so,  al  + ao);
            cpasync16(base + 16384 + so, BHi + bo);
            cpasync16(base + 24576 + so, BLo + bo);
        }
    };

    const int warp_m = wid & 1;
    const int warp_n = wid >> 1;
    const int arow   = warp_m * 32 + (lane & 15);
    const int akh    = lane >> 4;
    const int asw    = arow & 7;
    const u32 aoff0  = (u32)(arow * 128);
    const u32 aoff1  = (u32)((arow + 16) * 128);
    const int brow   = warp_n * 16 + (lane & 7) + ((lane >> 4) << 3);
    const int bkh    = (lane >> 3) & 1;
    const int bsw    = brow & 7;
    const u32 boff   = (u32)(brow * 128);

    float acc[2][2][4] = {};

    load_chunk(0, 0); CP_COMMIT();
    for (int c = 0; c < NC; c++) {
        CP_WAIT0();
        __syncthreads();
        if (c + 1 < NC) { load_chunk(c + 1, (c + 1) & 1); CP_COMMIT(); }

        const u32 Ah = sb + (c & 1) * 32768;
        const u32 Al = Ah + 8192;
        const u32 Bh = Ah + 16384;
        const u32 Bl = Ah + 24576;
#pragma unroll
        for (int kk = 0; kk < 4; kk++) {
            const u32 sa  = (((u32)(kk * 2 + akh) ^ (u32)asw) << 4);
            const u32 sbo = (((u32)(kk * 2 + bkh) ^ (u32)bsw) << 4);
            u32 ah0[4], ah1[4], al0[4], al1[4], bh[4], bl[4];
            LDSM4(ah0, Ah + aoff0 + sa);
            LDSM4(ah1, Ah + aoff1 + sa);
            LDSM4(al0, Al + aoff0 + sa);
            LDSM4(al1, Al + aoff1 + sa);
            LDSM4(bh,  Bh + boff + sbo);
            LDSM4(bl,  Bl + boff + sbo);
#pragma unroll
            for (int nt = 0; nt < 2; nt++) {
                MMA(acc[0][nt], ah0, bh[2 * nt], bh[2 * nt + 1]);
                MMA(acc[1][nt], ah1, bh[2 * nt], bh[2 * nt + 1]);
                MMA(acc[0][nt], ah0, bl[2 * nt], bl[2 * nt + 1]);
                MMA(acc[1][nt], ah1, bl[2 * nt], bl[2 * nt + 1]);
                MMA(acc[0][nt], al0, bh[2 * nt], bh[2 * nt + 1]);
                MMA(acc[1][nt], al1, bh[2 * nt], bh[2 * nt + 1]);
            }
        }
    }

#pragma unroll
    for (int mt = 0; mt < 2; mt++)
#pragma unroll
        for (int nt = 0; nt < 2; nt++) {
            const int gm = bm + warp_m * 32 + mt * 16 + (lane >> 2);
            const int gn = bn + warp_n * 16 + nt * 8 + 2 * (lane & 3);
            *reinterpret_cast<float2*>(&G[(size_t)gm * ldG + gn]) =
                make_float2(acc[mt][nt][0], acc[mt][nt][1]);
            *reinterpret_cast<float2*>(&G[(size_t)(gm + 8) * ldG + gn]) =
                make_float2(acc[mt][nt][2], acc[mt][nt][3]);
        }
}

// --------------------- epi bodies (R7 scalar, verbatim) ----------------------
__device__ __forceinline__ void epi1_body(
    int idx, const float* __restrict__ bmih, const float* __restrict__ bmhh, int t)
{
    const int b = idx >> 9, hc = idx & 511;
    const float* __restrict__ Ga = g_G1[0] + (size_t)b * N1;
    const float* __restrict__ Gb = g_G1[1] + (size_t)b * N1;
    const float* __restrict__ Gx = g_XW + ((size_t)t * B_ + b) * N1;

    float vi = sigf (Ga[hc]        + Gb[hc]        + __ldcs(Gx + hc)        + bmih[hc]        + bmhh[hc]);
    float vo = sigf (Ga[512 + hc]  + Gb[512 + hc]  + __ldcs(Gx + 512 + hc)  + bmih[512 + hc]  + bmhh[512 + hc]);
    float vg = tanhf(Ga[1024 + hc] + Gb[1024 + hc] + __ldcs(Gx + 1024 + hc) + bmih[1024 + hc] + bmhh[1024 + hc]);

    float fs = 0.0f;
#pragma unroll
    for (int j = 1; j <= KLAG; j++)
        fs = fmaf(g_wd[j - 1][hc], g_hist[(t - j) & (KLAG - 1)][idx], fs);

    float c1 = vi * vg - fs;
    g_hist[t & (KLAG - 1)][idx] = c1;
    float h1n = vo * tanhf(c1);
    split1(h1n, g_h1hi[idx], g_h1lo[idx]);
}

__device__ __forceinline__ void epi2_body(
    int idx, const float* __restrict__ bih, const float* __restrict__ bhh,
    const int* __restrict__ length, int t)
{
    const int b = idx >> 9, hc = idx & 511;
    const float* __restrict__ Ga = g_G2[0] + (size_t)b * N2;
    const float* __restrict__ Gb = g_G2[1] + (size_t)b * N2;

    float xi = sigf (Ga[hc]        + Gb[hc]        + bih[hc]        + bhh[hc]);
    float xf = sigf (Ga[512 + hc]  + Gb[512 + hc]  + bih[512 + hc]  + bhh[512 + hc]);
    float xg = tanhf(Ga[1024 + hc] + Gb[1024 + hc] + bih[1024 + hc] + bhh[1024 + hc]);
    float xo = sigf (Ga[1536 + hc] + Gb[1536 + hc] + bih[1536 + hc] + bhh[1536 + hc]);

    float cn = xf * g_c2[idx] + xi * xg;
    g_c2[idx] = cn;
    float hv = tanhf(xo * tanhf(cn));
    split1(hv, g_h2hi[idx], g_h2lo[idx]);
    if (length[b] == t) g_sel[idx] = hv;
}

// standalone epi1 (prologue, t = 0)
__global__ __launch_bounds__(256) void epi1_kernel(
    const float* __restrict__ bmih, const float* __restrict__ bmhh, int t)
{
    epi1_body(blockIdx.x * blockDim.x + threadIdx.x, bmih, bmhh, t);
}
// standalone epi2 (tail, t = T-1)
__global__ __launch_bounds__(256) void epi2_kernel(
    const float* __restrict__ bih, const float* __restrict__ bhh,
    const int* __restrict__ length, int t)
{
    epi2_body(blockIdx.x * blockDim.x + threadIdx.x, bih, bhh, length, t);
}
// fused: blocks [0,512) run epi1(t+1); blocks [512,1024) run epi2(t)
__global__ __launch_bounds__(256) void epiX_kernel(
    const float* __restrict__ bmih, const float* __restrict__ bmhh,
    const float* __restrict__ bih,  const float* __restrict__ bhh,
    const int* __restrict__ length, int t)
{
    const int blk = blockIdx.x;
    if (blk < 512) {
        epi1_body(blk * blockDim.x + threadIdx.x, bmih, bmhh, t + 1);
    } else {
        epi2_body((blk - 512) * blockDim.x + threadIdx.x, bih, bhh, length, t);
    }
}

// ------------------------------- head ---------------------------------------
__global__ __launch_bounds__(128) void head_kernel(
    const float* __restrict__ Wout, const float* __restrict__ bout,
    float* __restrict__ out)
{
    const int warp = (blockIdx.x * blockDim.x + threadIdx.x) >> 5;
    const int lane = threadIdx.x & 31;
    if (warp >= B_) return;

    float p[O_] = {0.f, 0.f, 0.f, 0.f, 0.f};
    for (int h = lane; h < H_; h += 32) {
        float s = g_sel[warp * H_ + h];
#pragma unroll
        for (int o = 0; o < O_; o++) p[o] = fmaf(s, Wout[o * H_ + h], p[o]);
    }
#pragma unroll
    for (int o = 0; o < O_; o++)
#pragma unroll
        for (int off = 16; off > 0; off >>= 1)
            p[o] += __shfl_xor_sync(0xffffffffu, p[o], off);

    if (lane == 0) {
        float l[O_], m = -1e30f;
#pragma unroll
        for (int o = 0; o < O_; o++) { l[o] = p[o] + bout[o]; m = fmaxf(m, l[o]); }
        float s = 0.0f;
#pragma unroll
        for (int o = 0; o < O_; o++) s += expf(l[o] - m);
        float ls = logf(s);
#pragma unroll
        for (int o = 0; o < O_; o++) out[warp * O_ + o] = l[o] - m - ls;
    }
}

// ----------------------------- launcher -------------------------------------
extern "C" void kernel_launch(void* const* d_in, const int* in_sizes, int n_in,
                              void* d_out, int out_size)
{
    const float* x    = (const float*)d_in[0];
    const int*   len  = (const int*)  d_in[1];
    const float* b_d  = (const float*)d_in[2];
    const float* Wmih = (const float*)d_in[3];
    const float* Wmhh = (const float*)d_in[4];
    const float* bmih = (const float*)d_in[5];
    const float* bmhh = (const float*)d_in[6];
    const float* Wih  = (const float*)d_in[7];
    const float* Whh  = (const float*)d_in[8];
    const float* bih  = (const float*)d_in[9];
    const float* bhh  = (const float*)d_in[10];
    const float* Wout = (const float*)d_in[11];
    const float* bout = (const float*)d_in[12];
    float* out = (float*)d_out;

    cudaFuncSetAttribute(gemmx_kernel,   cudaFuncAttributeMaxDynamicSharedMemorySize, SMEM_X);
    cudaFuncSetAttribute(gemm_kernel<1>, cudaFuncAttributeMaxDynamicSharedMemorySize, SMEM_S);
    cudaFuncSetAttribute(gemm_kernel<2>, cudaFuncAttributeMaxDynamicSharedMemorySize, SMEM_S);

    init_kernel<<<1024, 256>>>(b_d, x, Wmih, Wmhh, Wih, Whh);

    // hoisted input projection over all timesteps (throughput GEMM)
    gemmx_kernel<<<dim3(N1 / 128, (T_ * B_) / 128), 256, SMEM_X>>>();

    // prologue
    gemm_kernel<1><<<dim3(N1 / 64, 4, 2), 256, SMEM_S>>>(0);
    epi1_kernel<<<BH / 256, 256>>>(bmih, bmhh, 0);

    // main loop: g2(t) -> g1(t+1) -> eX(t) = epi2(t) || epi1(t+1)
    for (int t = 0; t < T_ - 1; t++) {
        gemm_kernel<2><<<dim3(N2 / 64, 4, 2), 256, SMEM_S>>>(t);
        gemm_kernel<1><<<dim3(N1 / 64, 4, 2), 256, SMEM_S>>>(t + 1);
        epiX_kernel<<<2 * (BH / 256), 256>>>(bmih, bmhh, bih, bhh, len, t);
    }

    // tail
    gemm_kernel<2><<<dim3(N2 / 64, 4, 2), 256, SMEM_S>>>(T_ - 1);
    epi2_kernel<<<BH / 256, 256>>>(bih, bhh, len, T_ - 1);

    head_kernel<<<64, 128>>>(Wout, bout, out);
}

// round 15
// speedup vs baseline: 1.8598x; 1.0785x over previous
#include <cuda_runtime.h>
#include <cuda_bf16.h>
#include <cstdint>

typedef uint32_t u32;
typedef uint64_t u64;
typedef unsigned short u16;

// ---------------------------------------------------------------------------
// MLSTMFixD round 15 = R14 (best, 3383us) + merged step GEMMs:
//  - g2(t) and g1(t+1) are mutually independent -> ONE 448-CTA launch
//    (bodies verbatim R7; dispatch by blockIdx.x)
//  - loop: gemmstep(t), eX(t)   (2 launches/step)
// ---------------------------------------------------------------------------

constexpr int T_   = 128;
constexpr int B_   = 256;
constexpr int I_   = 512;
constexpr int H_   = 512;
constexpr int O_   = 5;
constexpr int KLAG = 32;
constexpr int BH   = B_ * H_;
constexpr int N1   = 3 * H_;   // 1536
constexpr int N2   = 4 * H_;   // 2048

constexpr int SMEM_X = 3 * 65536;   // gemmx: 3 stages x 64KB
constexpr int SMEM_S = 2 * 32768;   // step gemms: 2 stages x 32KB

// ------------------------- device scratch (static) -------------------------
__device__ __align__(16) u16 g_xhi[T_ * B_ * I_], g_xlo[T_ * B_ * I_];
__device__ __align__(16) u16 g_WxHi[N1 * 512],  g_WxLo[N1 * 512];    // Wmih
__device__ __align__(16) u16 g_W1Hi[N1 * 512],  g_W1Lo[N1 * 512];    // Wmhh
__device__ __align__(16) u16 g_W2Hi[N2 * 1024], g_W2Lo[N2 * 1024];   // [Wih|Whh]
__device__ __align__(16) u16 g_h1hi[BH], g_h1lo[BH];
__device__ __align__(16) u16 g_h2hi[BH], g_h2lo[BH];
__device__ float g_c2[BH];
__device__ float g_sel[BH];
__device__ float g_hist[KLAG][BH];          // circular by (t & 31)
__device__ float g_wd[KLAG][H_];
__device__ float g_XW[(size_t)T_ * B_ * N1];  // x @ Wmih^T for all t (streamed)
__device__ float g_G1[2][B_ * N1];          // K-split partials
__device__ float g_G2[2][B_ * N2];

// ------------------------------- helpers ------------------------------------
__device__ __forceinline__ u32 smem_u32(const void* p) {
    u32 a;
    asm("{ .reg .u64 t; cvta.to.shared.u64 t, %1; cvt.u32.u64 %0, t; }" : "=r"(a) : "l"(p));
    return a;
}
__device__ __forceinline__ void cpasync16(u32 dst, const void* src) {
    asm volatile("cp.async.cg.shared.global [%0], [%1], 16;" :: "r"(dst), "l"(src));
}
#define CP_COMMIT() asm volatile("cp.async.commit_group;" ::: "memory")
#define CP_WAIT0()  asm volatile("cp.async.wait_group 0;" ::: "memory")
#define CP_WAIT1()  asm volatile("cp.async.wait_group 1;" ::: "memory")

#define LDSM4(r, addr) asm volatile(                                           \
    "ldmatrix.sync.aligned.m8n8.x4.shared.b16 {%0,%1,%2,%3}, [%4];"            \
    : "=r"((r)[0]), "=r"((r)[1]), "=r"((r)[2]), "=r"((r)[3]) : "r"(addr))

#define MMA(d, a, b0, b1) asm volatile(                                        \
    "mma.sync.aligned.m16n8k16.row.col.f32.bf16.bf16.f32 "                     \
    "{%0,%1,%2,%3}, {%4,%5,%6,%7}, {%8,%9}, {%0,%1,%2,%3};"                    \
    : "+f"((d)[0]), "+f"((d)[1]), "+f"((d)[2]), "+f"((d)[3])                   \
    : "r"((a)[0]), "r"((a)[1]), "r"((a)[2]), "r"((a)[3]), "r"(b0), "r"(b1))

__device__ __forceinline__ u16 bf16bits(__nv_bfloat16 v) {
    __nv_bfloat16_raw r = *reinterpret_cast<__nv_bfloat16_raw*>(&v);
    return r.x;
}
__device__ __forceinline__ void split1(float a, u16& h, u16& l) {
    __nv_bfloat16 bh = __float2bfloat16_rn(a);
    float r = a - __bfloat162float(bh);
    __nv_bfloat16 bl = __float2bfloat16_rn(r);
    h = bf16bits(bh);
    l = bf16bits(bl);
}
__device__ __forceinline__ void split4(float4 v, u32& h01, u32& h23, u32& l01, u32& l23) {
    u16 h0, l0, h1, l1, h2, l2, h3, l3;
    split1(v.x, h0, l0); split1(v.y, h1, l1);
    split1(v.z, h2, l2); split1(v.w, h3, l3);
    h01 = (u32)h0 | ((u32)h1 << 16);  h23 = (u32)h2 | ((u32)h3 << 16);
    l01 = (u32)l0 | ((u32)l1 << 16);  l23 = (u32)l2 | ((u32)l3 << 16);
}
__device__ __forceinline__ float sigf(float x) { return 1.0f / (1.0f + expf(-x)); }

// ------------------------------- init ---------------------------------------
__global__ __launch_bounds__(256) void init_kernel(
    const float* __restrict__ b_d,  const float* __restrict__ x,
    const float* __restrict__ Wmih, const float* __restrict__ Wmhh,
    const float* __restrict__ Wih,  const float* __restrict__ Whh)
{
    const int tid = blockIdx.x * blockDim.x + threadIdx.x;
    const int tot = gridDim.x * blockDim.x;

    const int ngx = T_ * B_ * I_ / 4;
    for (int i = tid; i < ngx; i += tot) {
        float4 v = reinterpret_cast<const float4*>(x)[i];
        u32 h01, h23, l01, l23; split4(v, h01, h23, l01, l23);
        reinterpret_cast<uint2*>(g_xhi)[i] = make_uint2(h01, h23);
        reinterpret_cast<uint2*>(g_xlo)[i] = make_uint2(l01, l23);
    }

    const int ngWx = N1 * 512 / 4;
    for (int i = tid; i < ngWx; i += tot) {
        float4 v = reinterpret_cast<const float4*>(Wmih)[i];
        u32 h01, h23, l01, l23; split4(v, h01, h23, l01, l23);
        reinterpret_cast<uint2*>(g_WxHi)[i] = make_uint2(h01, h23);
        reinterpret_cast<uint2*>(g_WxLo)[i] = make_uint2(l01, l23);
    }
    for (int i = tid; i < ngWx; i += tot) {
        float4 v = reinterpret_cast<const float4*>(Wmhh)[i];
        u32 h01, h23, l01, l23; split4(v, h01, h23, l01, l23);
        reinterpret_cast<uint2*>(g_W1Hi)[i] = make_uint2(h01, h23);
        reinterpret_cast<uint2*>(g_W1Lo)[i] = make_uint2(l01, l23);
    }
    const int ngW2 = N2 * 1024 / 4;
    for (int i = tid; i < ngW2; i += tot) {
        int e = i * 4;
        int n = e >> 10, k = e & 1023;
        const float* src = (k < 512) ? (Wih + (size_t)n * 512 + k)
                                     : (Whh + (size_t)n * 512 + (k - 512));
        float4 v = *reinterpret_cast<const float4*>(src);
        u32 h01, h23, l01, l23; split4(v, h01, h23, l01, l23);
        reinterpret_cast<uint2*>(g_W2Hi)[i] = make_uint2(h01, h23);
        reinterpret_cast<uint2*>(g_W2Lo)[i] = make_uint2(l01, l23);
    }

    float4 z4 = make_float4(0.f, 0.f, 0.f, 0.f);
    for (int i = tid; i < KLAG * BH / 4; i += tot)
        reinterpret_cast<float4*>(&g_hist[0][0])[i] = z4;
    for (int i = tid; i < BH / 4; i += tot) {
        reinterpret_cast<float4*>(g_c2)[i]  = z4;
        reinterpret_cast<float4*>(g_sel)[i] = z4;
        reinterpret_cast<uint2*>(g_h1hi)[i] = make_uint2(0u, 0u);
        reinterpret_cast<uint2*>(g_h1lo)[i] = make_uint2(0u, 0u);
        reinterpret_cast<uint2*>(g_h2hi)[i] = make_uint2(0u, 0u);
        reinterpret_cast<uint2*>(g_h2lo)[i] = make_uint2(0u, 0u);
    }

    if (tid < H_) {
        float d = 0.5f * (1.0f / (1.0f + expf(-b_d[tid])));
        float c = 1.0f;
        for (int j = 1; j <= KLAG; j++) {
            c *= ((float)(j - 1) - d) / (float)j;
            g_wd[j - 1][tid] = c;
        }
    }
}

// ------------------- XW precompute (R13 throughput GEMM) ---------------------
__global__ __launch_bounds__(256, 1) void gemmx_kernel()
{
    extern __shared__ __align__(128) char smem[];
    const u32 sb  = smem_u32(smem);
    const int tid = threadIdx.x;
    const int wid = tid >> 5, lane = tid & 31;
    const int bn  = blockIdx.x * 128;
    const int bm  = blockIdx.y * 128;

    auto load_chunk = [&](int c, int stage) {
        const int k0 = c * 64;
        const u32 base = sb + stage * 65536;
#pragma unroll
        for (int it = 0; it < 4; it++) {
            const int u = tid + it * 256;
            const int r = u >> 3, cu = u & 7;
            const u32 so = (u32)(r * 128 + ((cu ^ (r & 7)) << 4));
            const size_t ao = (size_t)(bm + r) * 512 + k0 + cu * 8;
            const size_t bo = (size_t)(bn + r) * 512 + k0 + cu * 8;
            cpasync16(base + so,         g_xhi  + ao);
            cpasync16(base + 16384 + so, g_xlo  + ao);
            cpasync16(base + 32768 + so, g_WxHi + bo);
            cpasync16(base + 49152 + so, g_WxLo + bo);
        }
    };

    const int warp_m = wid & 1;
    const int warp_n = wid >> 1;
    const int arow0  = warp_m * 64 + (lane & 15);
    const int akh    = lane >> 4;
    const int asw    = arow0 & 7;
    const int brow0  = warp_n * 32 + (lane & 7) + ((lane >> 4) << 3);
    const int bkh    = (lane >> 3) & 1;
    const int bsw    = brow0 & 7;

    float acc[4][4][4] = {};

    load_chunk(0, 0); CP_COMMIT();
    load_chunk(1, 1); CP_COMMIT();

    for (int c = 0; c < 8; c++) {
        if (c + 1 < 8) { CP_WAIT1(); } else { CP_WAIT0(); }
        __syncthreads();
        if (c + 2 < 8) { load_chunk(c + 2, (c + 2) % 3); CP_COMMIT(); }

        const u32 Ah = sb + (c % 3) * 65536;
        const u32 Al = Ah + 16384;
        const u32 Bh = Ah + 32768;
        const u32 Bl = Ah + 49152;

#pragma unroll
        for (int kk = 0; kk < 4; kk++) {
            const u32 sa  = (((u32)(kk * 2 + akh) ^ (u32)asw) << 4);
            const u32 sbo = (((u32)(kk * 2 + bkh) ^ (u32)bsw) << 4);

            u32 ah[4][4], al[4][4], bh[2][4], bl[2][4];
#pragma unroll
            for (int mf = 0; mf < 4; mf++) {
                const u32 ro = (u32)((arow0 + mf * 16) * 128);
                LDSM4(ah[mf], Ah + ro + sa);
                LDSM4(al[mf], Al + ro + sa);
            }
#pragma unroll
            for (int bf = 0; bf < 2; bf++) {
                const u32 ro = (u32)((brow0 + bf * 16) * 128);
                LDSM4(bh[bf], Bh + ro + sbo);
                LDSM4(bl[bf], Bl + ro + sbo);
            }
#pragma unroll
            for (int mf = 0; mf < 4; mf++)
#pragma unroll
                for (int bf = 0; bf < 2; bf++)
#pragma unroll
                    for (int n8 = 0; n8 < 2; n8++) {
                        float* d = acc[mf][bf * 2 + n8];
                        MMA(d, ah[mf], bh[bf][2 * n8], bh[bf][2 * n8 + 1]);
                        MMA(d, ah[mf], bl[bf][2 * n8], bl[bf][2 * n8 + 1]);
                        MMA(d, al[mf], bh[bf][2 * n8], bh[bf][2 * n8 + 1]);
                    }
        }
    }

#pragma unroll
    for (int mf = 0; mf < 4; mf++)
#pragma unroll
        for (int j = 0; j < 4; j++) {
            const int gm = bm + warp_m * 64 + mf * 16 + (lane >> 2);
            const int gn = bn + warp_n * 32 + j * 8 + 2 * (lane & 3);
            __stcs(reinterpret_cast<float2*>(&g_XW[(size_t)gm * N1 + gn]),
                   make_float2(acc[mf][j][0], acc[mf][j][1]));
            __stcs(reinterpret_cast<float2*>(&g_XW[(size_t)(gm + 8) * N1 + gn]),
                   make_float2(acc[mf][j][2], acc[mf][j][3]));
        }
}

// ----------------- step GEMM body (R7, verbatim; device inline) --------------
template <int SET>
__device__ __forceinline__ void gemm_body(char* smem, int bnT, int bmT, int kz)
{
    constexpr int NC  = (SET == 1) ? 4 : 8;
    constexpr int ldB = (SET == 2) ? 1024 : 512;
    constexpr int ldG = (SET == 2) ? N2 : N1;

    const u32 sb  = smem_u32(smem);
    const int tid = threadIdx.x;
    const int wid = tid >> 5, lane = tid & 31;
    const int bn  = bnT * 64;
    const int bm  = bmT * 64;
    const int kbase = (SET == 1) ? kz * 256 : kz * 512;

    const u16* __restrict__ BHi = (SET == 1) ? g_W1Hi : g_W2Hi;
    const u16* __restrict__ BLo = (SET == 1) ? g_W1Lo : g_W2Lo;
    float* __restrict__ G = (SET == 1) ? g_G1[kz] : g_G2[kz];

    const int lr  = tid >> 3;
    const int lcu = tid & 7;
    auto load_chunk = [&](int c, int stage) {
        const int k0 = kbase + c * 64;
        const u16* ah; const u16* al; int kloc;
        if (SET == 2 && k0 >= 512) { ah = g_h2hi; al = g_h2lo; kloc = k0 - 512; }
        else                       { ah = g_h1hi; al = g_h1lo; kloc = k0;       }
        const u32 base = sb + stage * 32768;
#pragma unroll
        for (int j = 0; j < 2; j++) {
            const int r = lr + j * 32;
            const u32 so = (u32)(r * 128 + ((lcu ^ (r & 7)) << 4));
            const size_t ao = (size_t)(bm + r) * 512 + kloc + lcu * 8;
            const size_t bo = (size_t)(bn + r) * ldB + k0 + lcu * 8;
            cpasync16(base + so,         ah  + ao);
            cpasync16(base + 8192 + so,  al  + ao);
            cpasync16(base + 16384 + so, BHi + bo);
            cpasync16(base + 24576 + so, BLo + bo);
        }
    };

    const int warp_m = wid & 1;
    const int warp_n = wid >> 1;
    const int arow   = warp_m * 32 + (lane & 15);
    const int akh    = lane >> 4;
    const int asw    = arow & 7;
    const u32 aoff0  = (u32)(arow * 128);
    const u32 aoff1  = (u32)((arow + 16) * 128);
    const int brow   = warp_n * 16 + (lane & 7) + ((lane >> 4) << 3);
    const int bkh    = (lane >> 3) & 1;
    const int bsw    = brow & 7;
    const u32 boff   = (u32)(brow * 128);

    float acc[2][2][4] = {};

    load_chunk(0, 0); CP_COMMIT();
    for (int c = 0; c < NC; c++) {
        CP_WAIT0();
        __syncthreads();
        if (c + 1 < NC) { load_chunk(c + 1, (c + 1) & 1); CP_COMMIT(); }

        const u32 Ah = sb + (c & 1) * 32768;
        const u32 Al = Ah + 8192;
        const u32 Bh = Ah + 16384;
        const u32 Bl = Ah + 24576;
#pragma unroll
        for (int kk = 0; kk < 4; kk++) {
            const u32 sa  = (((u32)(kk * 2 + akh) ^ (u32)asw) << 4);
            const u32 sbo = (((u32)(kk * 2 + bkh) ^ (u32)bsw) << 4);
            u32 ah0[4], ah1[4], al0[4], al1[4], bh[4], bl[4];
            LDSM4(ah0, Ah + aoff0 + sa);
            LDSM4(ah1, Ah + aoff1 + sa);
            LDSM4(al0, Al + aoff0 + sa);
            LDSM4(al1, Al + aoff1 + sa);
            LDSM4(bh,  Bh + boff + sbo);
            LDSM4(bl,  Bl + boff + sbo);
#pragma unroll
            for (int nt = 0; nt < 2; nt++) {
                MMA(acc[0][nt], ah0, bh[2 * nt], bh[2 * nt + 1]);
                MMA(acc[1][nt], ah1, bh[2 * nt], bh[2 * nt + 1]);
                MMA(acc[0][nt], ah0, bl[2 * nt], bl[2 * nt + 1]);
                MMA(acc[1][nt], ah1, bl[2 * nt], bl[2 * nt + 1]);
                MMA(acc[0][nt], al0, bh[2 * nt], bh[2 * nt + 1]);
                MMA(acc[1][nt], al1, bh[2 * nt], bh[2 * nt + 1]);
            }
        }
    }

#pragma unroll
    for (int mt = 0; mt < 2; mt++)
#pragma unroll
        for (int nt = 0; nt < 2; nt++) {
            const int gm = bm + warp_m * 32 + mt * 16 + (lane >> 2);
            const int gn = bn + warp_n * 16 + nt * 8 + 2 * (lane & 3);
            *reinterpret_cast<float2*>(&G[(size_t)gm * ldG + gn]) =
                make_float2(acc[mt][nt][0], acc[mt][nt][1]);
            *reinterpret_cast<float2*>(&G[(size_t)(gm + 8) * ldG + gn]) =
                make_float2(acc[mt][nt][2], acc[mt][nt][3]);
        }
}

// standalone step GEMMs (prologue/tail)
template <int SET>
__global__ __launch_bounds__(256, 2) void gemm_kernel()
{
    extern __shared__ __align__(128) char smem[];
    gemm_body<SET>(smem, blockIdx.x, blockIdx.y, blockIdx.z);
}

// merged: blocks x<32 run g2(t) tile x; x>=32 run g1(t+1) tile x-32.
__global__ __launch_bounds__(256, 2) void gemmstep_kernel()
{
    extern __shared__ __align__(128) char smem[];
    if (blockIdx.x < 32) gemm_body<2>(smem, blockIdx.x, blockIdx.y, blockIdx.z);
    else                 gemm_body<1>(smem, blockIdx.x - 32, blockIdx.y, blockIdx.z);
}

// --------------------- epi bodies (R7 scalar, verbatim) ----------------------
__device__ __forceinline__ void epi1_body(
    int idx, const float* __restrict__ bmih, const float* __restrict__ bmhh, int t)
{
    const int b = idx >> 9, hc = idx & 511;
    const float* __restrict__ Ga = g_G1[0] + (size_t)b * N1;
    const float* __restrict__ Gb = g_G1[1] + (size_t)b * N1;
    const float* __restrict__ Gx = g_XW + ((size_t)t * B_ + b) * N1;

    float vi = sigf (Ga[hc]        + Gb[hc]        + __ldcs(Gx + hc)        + bmih[hc]        + bmhh[hc]);
    float vo = sigf (Ga[512 + hc]  + Gb[512 + hc]  + __ldcs(Gx + 512 + hc)  + bmih[512 + hc]  + bmhh[512 + hc]);
    float vg = tanhf(Ga[1024 + hc] + Gb[1024 + hc] + __ldcs(Gx + 1024 + hc) + bmih[1024 + hc] + bmhh[1024 + hc]);

    float fs = 0.0f;
#pragma unroll
    for (int j = 1; j <= KLAG; j++)
        fs = fmaf(g_wd[j - 1][hc], g_hist[(t - j) & (KLAG - 1)][idx], fs);

    float c1 = vi * vg - fs;
    g_hist[t & (KLAG - 1)][idx] = c1;
    float h1n = vo * tanhf(c1);
    split1(h1n, g_h1hi[idx], g_h1lo[idx]);
}

__device__ __forceinline__ void epi2_body(
    int idx, const float* __restrict__ bih, const float* __restrict__ bhh,
    const int* __restrict__ length, int t)
{
    const int b = idx >> 9, hc = idx & 511;
    const float* __restrict__ Ga = g_G2[0] + (size_t)b * N2;
    const float* __restrict__ Gb = g_G2[1] + (size_t)b * N2;

    float xi = sigf (Ga[hc]        + Gb[hc]        + bih[hc]        + bhh[hc]);
    float xf = sigf (Ga[512 + hc]  + Gb[512 + hc]  + bih[512 + hc]  + bhh[512 + hc]);
    float xg = tanhf(Ga[1024 + hc] + Gb[1024 + hc] + bih[1024 + hc] + bhh[1024 + hc]);
    float xo = sigf (Ga[1536 + hc] + Gb[1536 + hc] + bih[1536 + hc] + bhh[1536 + hc]);

    float cn = xf * g_c2[idx] + xi * xg;
    g_c2[idx] = cn;
    float hv = tanhf(xo * tanhf(cn));
    split1(hv, g_h2hi[idx], g_h2lo[idx]);
    if (length[b] == t) g_sel[idx] = hv;
}

__global__ __launch_bounds__(256) void epi1_kernel(
    const float* __restrict__ bmih, const float* __restrict__ bmhh, int t)
{
    epi1_body(blockIdx.x * blockDim.x + threadIdx.x, bmih, bmhh, t);
}
__global__ __launch_bounds__(256) void epi2_kernel(
    const float* __restrict__ bih, const float* __restrict__ bhh,
    const int* __restrict__ length, int t)
{
    epi2_body(blockIdx.x * blockDim.x + threadIdx.x, bih, bhh, length, t);
}
// fused: blocks [0,512) run epi1(t+1); blocks [512,1024) run epi2(t)
__global__ __launch_bounds__(256) void epiX_kernel(
    const float* __restrict__ bmih, const float* __restrict__ bmhh,
    const float* __restrict__ bih,  const float* __restrict__ bhh,
    const int* __restrict__ length, int t)
{
    const int blk = blockIdx.x;
    if (blk < 512) {
        epi1_body(blk * blockDim.x + threadIdx.x, bmih, bmhh, t + 1);
    } else {
        epi2_body((blk - 512) * blockDim.x + threadIdx.x, bih, bhh, length, t);
    }
}

// ------------------------------- head ---------------------------------------
__global__ __launch_bounds__(128) void head_kernel(
    const float* __restrict__ Wout, const float* __restrict__ bout,
    float* __restrict__ out)
{
    const int warp = (blockIdx.x * blockDim.x + threadIdx.x) >> 5;
    const int lane = threadIdx.x & 31;
    if (warp >= B_) return;

    float p[O_] = {0.f, 0.f, 0.f, 0.f, 0.f};
    for (int h = lane; h < H_; h += 32) {
        float s = g_sel[warp * H_ + h];
#pragma unroll
        for (int o = 0; o < O_; o++) p[o] = fmaf(s, Wout[o * H_ + h], p[o]);
    }
#pragma unroll
    for (int o = 0; o < O_; o++)
#pragma unroll
        for (int off = 16; off > 0; off >>= 1)
            p[o] += __shfl_xor_sync(0xffffffffu, p[o], off);

    if (lane == 0) {
        float l[O_], m = -1e30f;
#pragma unroll
        for (int o = 0; o < O_; o++) { l[o] = p[o] + bout[o]; m = fmaxf(m, l[o]); }
        float s = 0.0f;
#pragma unroll
        for (int o = 0; o < O_; o++) s += expf(l[o] - m);
        float ls = logf(s);
#pragma unroll
        for (int o = 0; o < O_; o++) out[warp * O_ + o] = l[o] - m - ls;
    }
}

// ----------------------------- launcher -------------------------------------
extern "C" void kernel_launch(void* const* d_in, const int* in_sizes, int n_in,
                              void* d_out, int out_size)
{
    const float* x    = (const float*)d_in[0];
    const int*   len  = (const int*)  d_in[1];
    const float* b_d  = (const float*)d_in[2];
    const float* Wmih = (const float*)d_in[3];
    const float* Wmhh = (const float*)d_in[4];
    const float* bmih = (const float*)d_in[5];
    const float* bmhh = (const float*)d_in[6];
    const float* Wih  = (const float*)d_in[7];
    const float* Whh  = (const float*)d_in[8];
    const float* bih  = (const float*)d_in[9];
    const float* bhh  = (const float*)d_in[10];
    const float* Wout = (const float*)d_in[11];
    const float* bout = (const float*)d_in[12];
    float* out = (float*)d_out;

    cudaFuncSetAttribute(gemmx_kernel,    cudaFuncAttributeMaxDynamicSharedMemorySize, SMEM_X);
    cudaFuncSetAttribute(gemm_kernel<1>,  cudaFuncAttributeMaxDynamicSharedMemorySize, SMEM_S);
    cudaFuncSetAttribute(gemm_kernel<2>,  cudaFuncAttributeMaxDynamicSharedMemorySize, SMEM_S);
    cudaFuncSetAttribute(gemmstep_kernel, cudaFuncAttributeMaxDynamicSharedMemorySize, SMEM_S);

    init_kernel<<<1024, 256>>>(b_d, x, Wmih, Wmhh, Wih, Whh);

    // hoisted input projection over all timesteps (throughput GEMM)
    gemmx_kernel<<<dim3(N1 / 128, (T_ * B_) / 128), 256, SMEM_X>>>();

    // prologue: g1(0), epi1(0)
    gemm_kernel<1><<<dim3(N1 / 64, 4, 2), 256, SMEM_S>>>();
    epi1_kernel<<<BH / 256, 256>>>(bmih, bmhh, 0);

    // main loop: [g2(t) || g1(t+1)] -> [epi2(t) || epi1(t+1)]
    for (int t = 0; t < T_ - 1; t++) {
        gemmstep_kernel<<<dim3(32 + 24, 4, 2), 256, SMEM_S>>>();
        epiX_kernel<<<2 * (BH / 256), 256>>>(bmih, bmhh, bih, bhh, len, t);
    }

    // tail: g2(T-1), epi2(T-1)
    gemm_kernel<2><<<dim3(N2 / 64, 4, 2), 256, SMEM_S>>>();
    epi2_kernel<<<BH / 256, 256>>>(bih, bhh, len, T_ - 1);

    head_kernel<<<64, 128>>>(Wout, bout, out);
}

// round 16
// speedup vs baseline: 1.9186x; 1.0316x over previous
#include <cuda_runtime.h>
#include <cuda_bf16.h>
#include <cstdint>

typedef uint32_t u32;
typedef uint64_t u64;
typedef unsigned short u16;

// ---------------------------------------------------------------------------
// MLSTMFixD round 16 = R15 (best, 3137us) + gemmstep at 3 CTAs/SM:
//  - __launch_bounds__(256,3) on the merged step GEMM (448 CTAs / 444 slots
//    = 1.01 waves instead of 1.51) — single change vs R15.
// ---------------------------------------------------------------------------

constexpr int T_   = 128;
constexpr int B_   = 256;
constexpr int I_   = 512;
constexpr int H_   = 512;
constexpr int O_   = 5;
constexpr int KLAG = 32;
constexpr int BH   = B_ * H_;
constexpr int N1   = 3 * H_;   // 1536
constexpr int N2   = 4 * H_;   // 2048

constexpr int SMEM_X = 3 * 65536;   // gemmx: 3 stages x 64KB
constexpr int SMEM_S = 2 * 32768;   // step gemms: 2 stages x 32KB

// ------------------------- device scratch (static) -------------------------
__device__ __align__(16) u16 g_xhi[T_ * B_ * I_], g_xlo[T_ * B_ * I_];
__device__ __align__(16) u16 g_WxHi[N1 * 512],  g_WxLo[N1 * 512];    // Wmih
__device__ __align__(16) u16 g_W1Hi[N1 * 512],  g_W1Lo[N1 * 512];    // Wmhh
__device__ __align__(16) u16 g_W2Hi[N2 * 1024], g_W2Lo[N2 * 1024];   // [Wih|Whh]
__device__ __align__(16) u16 g_h1hi[BH], g_h1lo[BH];
__device__ __align__(16) u16 g_h2hi[BH], g_h2lo[BH];
__device__ float g_c2[BH];
__device__ float g_sel[BH];
__device__ float g_hist[KLAG][BH];          // circular by (t & 31)
__device__ float g_wd[KLAG][H_];
__device__ float g_XW[(size_t)T_ * B_ * N1];  // x @ Wmih^T for all t (streamed)
__device__ float g_G1[2][B_ * N1];          // K-split partials
__device__ float g_G2[2][B_ * N2];

// ------------------------------- helpers ------------------------------------
__device__ __forceinline__ u32 smem_u32(const void* p) {
    u32 a;
    asm("{ .reg .u64 t; cvta.to.shared.u64 t, %1; cvt.u32.u64 %0, t; }" : "=r"(a) : "l"(p));
    return a;
}
__device__ __forceinline__ void cpasync16(u32 dst, const void* src) {
    asm volatile("cp.async.cg.shared.global [%0], [%1], 16;" :: "r"(dst), "l"(src));
}
#define CP_COMMIT() asm volatile("cp.async.commit_group;" ::: "memory")
#define CP_WAIT0()  asm volatile("cp.async.wait_group 0;" ::: "memory")
#define CP_WAIT1()  asm volatile("cp.async.wait_group 1;" ::: "memory")

#define LDSM4(r, addr) asm volatile(                                           \
    "ldmatrix.sync.aligned.m8n8.x4.shared.b16 {%0,%1,%2,%3}, [%4];"            \
    : "=r"((r)[0]), "=r"((r)[1]), "=r"((r)[2]), "=r"((r)[3]) : "r"(addr))

#define MMA(d, a, b0, b1) asm volatile(                                        \
    "mma.sync.aligned.m16n8k16.row.col.f32.bf16.bf16.f32 "                     \
    "{%0,%1,%2,%3}, {%4,%5,%6,%7}, {%8,%9}, {%0,%1,%2,%3};"                    \
    : "+f"((d)[0]), "+f"((d)[1]), "+f"((d)[2]), "+f"((d)[3])                   \
    : "r"((a)[0]), "r"((a)[1]), "r"((a)[2]), "r"((a)[3]), "r"(b0), "r"(b1))

__device__ __forceinline__ u16 bf16bits(__nv_bfloat16 v) {
    __nv_bfloat16_raw r = *reinterpret_cast<__nv_bfloat16_raw*>(&v);
    return r.x;
}
__device__ __forceinline__ void split1(float a, u16& h, u16& l) {
    __nv_bfloat16 bh = __float2bfloat16_rn(a);
    float r = a - __bfloat162float(bh);
    __nv_bfloat16 bl = __float2bfloat16_rn(r);
    h = bf16bits(bh);
    l = bf16bits(bl);
}
__device__ __forceinline__ void split4(float4 v, u32& h01, u32& h23, u32& l01, u32& l23) {
    u16 h0, l0, h1, l1, h2, l2, h3, l3;
    split1(v.x, h0, l0); split1(v.y, h1, l1);
    split1(v.z, h2, l2); split1(v.w, h3, l3);
    h01 = (u32)h0 | ((u32)h1 << 16);  h23 = (u32)h2 | ((u32)h3 << 16);
    l01 = (u32)l0 | ((u32)l1 << 16);  l23 = (u32)l2 | ((u32)l3 << 16);
}
__device__ __forceinline__ float sigf(float x) { return 1.0f / (1.0f + expf(-x)); }

// ------------------------------- init ---------------------------------------
__global__ __launch_bounds__(256) void init_kernel(
    const float* __restrict__ b_d,  const float* __restrict__ x,
    const float* __restrict__ Wmih, const float* __restrict__ Wmhh,
    const float* __restrict__ Wih,  const float* __restrict__ Whh)
{
    const int tid = blockIdx.x * blockDim.x + threadIdx.x;
    const int tot = gridDim.x * blockDim.x;

    const int ngx = T_ * B_ * I_ / 4;
    for (int i = tid; i < ngx; i += tot) {
        float4 v = reinterpret_cast<const float4*>(x)[i];
        u32 h01, h23, l01, l23; split4(v, h01, h23, l01, l23);
        reinterpret_cast<uint2*>(g_xhi)[i] = make_uint2(h01, h23);
        reinterpret_cast<uint2*>(g_xlo)[i] = make_uint2(l01, l23);
    }

    const int ngWx = N1 * 512 / 4;
    for (int i = tid; i < ngWx; i += tot) {
        float4 v = reinterpret_cast<const float4*>(Wmih)[i];
        u32 h01, h23, l01, l23; split4(v, h01, h23, l01, l23);
        reinterpret_cast<uint2*>(g_WxHi)[i] = make_uint2(h01, h23);
        reinterpret_cast<uint2*>(g_WxLo)[i] = make_uint2(l01, l23);
    }
    for (int i = tid; i < ngWx; i += tot) {
        float4 v = reinterpret_cast<const float4*>(Wmhh)[i];
        u32 h01, h23, l01, l23; split4(v, h01, h23, l01, l23);
        reinterpret_cast<uint2*>(g_W1Hi)[i] = make_uint2(h01, h23);
        reinterpret_cast<uint2*>(g_W1Lo)[i] = make_uint2(l01, l23);
    }
    const int ngW2 = N2 * 1024 / 4;
    for (int i = tid; i < ngW2; i += tot) {
        int e = i * 4;
        int n = e >> 10, k = e & 1023;
        const float* src = (k < 512) ? (Wih + (size_t)n * 512 + k)
                                     : (Whh + (size_t)n * 512 + (k - 512));
        float4 v = *reinterpret_cast<const float4*>(src);
        u32 h01, h23, l01, l23; split4(v, h01, h23, l01, l23);
        reinterpret_cast<uint2*>(g_W2Hi)[i] = make_uint2(h01, h23);
        reinterpret_cast<uint2*>(g_W2Lo)[i] = make_uint2(l01, l23);
    }

    float4 z4 = make_float4(0.f, 0.f, 0.f, 0.f);
    for (int i = tid; i < KLAG * BH / 4; i += tot)
        reinterpret_cast<float4*>(&g_hist[0][0])[i] = z4;
    for (int i = tid; i < BH / 4; i += tot) {
        reinterpret_cast<float4*>(g_c2)[i]  = z4;
        reinterpret_cast<float4*>(g_sel)[i] = z4;
        reinterpret_cast<uint2*>(g_h1hi)[i] = make_uint2(0u, 0u);
        reinterpret_cast<uint2*>(g_h1lo)[i] = make_uint2(0u, 0u);
        reinterpret_cast<uint2*>(g_h2hi)[i] = make_uint2(0u, 0u);
        reinterpret_cast<uint2*>(g_h2lo)[i] = make_uint2(0u, 0u);
    }

    if (tid < H_) {
        float d = 0.5f * (1.0f / (1.0f + expf(-b_d[tid])));
        float c = 1.0f;
        for (int j = 1; j <= KLAG; j++) {
            c *= ((float)(j - 1) - d) / (float)j;
            g_wd[j - 1][tid] = c;
        }
    }
}

// ------------------- XW precompute (R13 throughput GEMM) ---------------------
__global__ __launch_bounds__(256, 1) void gemmx_kernel()
{
    extern __shared__ __align__(128) char smem[];
    const u32 sb  = smem_u32(smem);
    const int tid = threadIdx.x;
    const int wid = tid >> 5, lane = tid & 31;
    const int bn  = blockIdx.x * 128;
    const int bm  = blockIdx.y * 128;

    auto load_chunk = [&](int c, int stage) {
        const int k0 = c * 64;
        const u32 base = sb + stage * 65536;
#pragma unroll
        for (int it = 0; it < 4; it++) {
            const int u = tid + it * 256;
            const int r = u >> 3, cu = u & 7;
            const u32 so = (u32)(r * 128 + ((cu ^ (r & 7)) << 4));
            const size_t ao = (size_t)(bm + r) * 512 + k0 + cu * 8;
            const size_t bo = (size_t)(bn + r) * 512 + k0 + cu * 8;
            cpasync16(base + so,         g_xhi  + ao);
            cpasync16(base + 16384 + so, g_xlo  + ao);
            cpasync16(base + 32768 + so, g_WxHi + bo);
            cpasync16(base + 49152 + so, g_WxLo + bo);
        }
    };

    const int warp_m = wid & 1;
    const int warp_n = wid >> 1;
    const int arow0  = warp_m * 64 + (lane & 15);
    const int akh    = lane >> 4;
    const int asw    = arow0 & 7;
    const int brow0  = warp_n * 32 + (lane & 7) + ((lane >> 4) << 3);
    const int bkh    = (lane >> 3) & 1;
    const int bsw    = brow0 & 7;

    float acc[4][4][4] = {};

    load_chunk(0, 0); CP_COMMIT();
    load_chunk(1, 1); CP_COMMIT();

    for (int c = 0; c < 8; c++) {
        if (c + 1 < 8) { CP_WAIT1(); } else { CP_WAIT0(); }
        __syncthreads();
        if (c + 2 < 8) { load_chunk(c + 2, (c + 2) % 3); CP_COMMIT(); }

        const u32 Ah = sb + (c % 3) * 65536;
        const u32 Al = Ah + 16384;
        const u32 Bh = Ah + 32768;
        const u32 Bl = Ah + 49152;

#pragma unroll
        for (int kk = 0; kk < 4; kk++) {
            const u32 sa  = (((u32)(kk * 2 + akh) ^ (u32)asw) << 4);
            const u32 sbo = (((u32)(kk * 2 + bkh) ^ (u32)bsw) << 4);

            u32 ah[4][4], al[4][4], bh[2][4], bl[2][4];
#pragma unroll
            for (int mf = 0; mf < 4; mf++) {
                const u32 ro = (u32)((arow0 + mf * 16) * 128);
                LDSM4(ah[mf], Ah + ro + sa);
                LDSM4(al[mf], Al + ro + sa);
            }
#pragma unroll
            for (int bf = 0; bf < 2; bf++) {
                const u32 ro = (u32)((brow0 + bf * 16) * 128);
                LDSM4(bh[bf], Bh + ro + sbo);
                LDSM4(bl[bf], Bl + ro + sbo);
            }
#pragma unroll
            for (int mf = 0; mf < 4; mf++)
#pragma unroll
                for (int bf = 0; bf < 2; bf++)
#pragma unroll
                    for (int n8 = 0; n8 < 2; n8++) {
                        float* d = acc[mf][bf * 2 + n8];
                        MMA(d, ah[mf], bh[bf][2 * n8], bh[bf][2 * n8 + 1]);
                        MMA(d, ah[mf], bl[bf][2 * n8], bl[bf][2 * n8 + 1]);
                        MMA(d, al[mf], bh[bf][2 * n8], bh[bf][2 * n8 + 1]);
                    }
        }
    }

#pragma unroll
    for (int mf = 0; mf < 4; mf++)
#pragma unroll
        for (int j = 0; j < 4; j++) {
            const int gm = bm + warp_m * 64 + mf * 16 + (lane >> 2);
            const int gn = bn + warp_n * 32 + j * 8 + 2 * (lane & 3);
            __stcs(reinterpret_cast<float2*>(&g_XW[(size_t)gm * N1 + gn]),
                   make_float2(acc[mf][j][0], acc[mf][j][1]));
            __stcs(reinterpret_cast<float2*>(&g_XW[(size_t)(gm + 8) * N1 + gn]),
                   make_float2(acc[mf][j][2], acc[mf][j][3]));
        }
}

// ----------------- step GEMM body (R7, verbatim; device inline) --------------
template <int SET>
__device__ __forceinline__ void gemm_body(char* smem, int bnT, int bmT, int kz)
{
    constexpr int NC  = (SET == 1) ? 4 : 8;
    constexpr int ldB = (SET == 2) ? 1024 : 512;
    constexpr int ldG = (SET == 2) ? N2 : N1;

    const u32 sb  = smem_u32(smem);
    const int tid = threadIdx.x;
    const int wid = tid >> 5, lane = tid & 31;
    const int bn  = bnT * 64;
    const int bm  = bmT * 64;
    const int kbase = (SET == 1) ? kz * 256 : kz * 512;

    const u16* __restrict__ BHi = (SET == 1) ? g_W1Hi : g_W2Hi;
    const u16* __restrict__ BLo = (SET == 1) ? g_W1Lo : g_W2Lo;
    float* __restrict__ G = (SET == 1) ? g_G1[kz] : g_G2[kz];

    const int lr  = tid >> 3;
    const int lcu = tid & 7;
    auto load_chunk = [&](int c, int stage) {
        const int k0 = kbase + c * 64;
        const u16* ah; const u16* al; int kloc;
        if (SET == 2 && k0 >= 512) { ah = g_h2hi; al = g_h2lo; kloc = k0 - 512; }
        else                       { ah = g_h1hi; al = g_h1lo; kloc = k0;       }
        const u32 base = sb + stage * 32768;
#pragma unroll
        for (int j = 0; j < 2; j++) {
            const int r = lr + j * 32;
            const u32 so = (u32)(r * 128 + ((lcu ^ (r & 7)) << 4));
            const size_t ao = (size_t)(bm + r) * 512 + kloc + lcu * 8;
            const size_t bo = (size_t)(bn + r) * ldB + k0 + lcu * 8;
            cpasync16(base + so,         ah  + ao);
            cpasync16(base + 8192 + so,  al  + ao);
            cpasync16(base + 16384 + so, BHi + bo);
            cpasync16(base + 24576 + so, BLo + bo);
        }
    };

    const int warp_m = wid & 1;
    const int warp_n = wid >> 1;
    const int arow   = warp_m * 32 + (lane & 15);
    const int akh    = lane >> 4;
    const int asw    = arow & 7;
    const u32 aoff0  = (u32)(arow * 128);
    const u32 aoff1  = (u32)((arow + 16) * 128);
    const int brow   = warp_n * 16 + (lane & 7) + ((lane >> 4) << 3);
    const int bkh    = (lane >> 3) & 1;
    const int bsw    = brow & 7;
    const u32 boff   = (u32)(brow * 128);

    float acc[2][2][4] = {};

    load_chunk(0, 0); CP_COMMIT();
    for (int c = 0; c < NC; c++) {
        CP_WAIT0();
        __syncthreads();
        if (c + 1 < NC) { load_chunk(c + 1, (c + 1) & 1); CP_COMMIT(); }

        const u32 Ah = sb + (c & 1) * 32768;
        const u32 Al = Ah + 8192;
        const u32 Bh = Ah + 16384;
        const u32 Bl = Ah + 24576;
#pragma unroll
        for (int kk = 0; kk < 4; kk++) {
            const u32 sa  = (((u32)(kk * 2 + akh) ^ (u32)asw) << 4);
            const u32 sbo = (((u32)(kk * 2 + bkh) ^ (u32)bsw) << 4);
            u32 ah0[4], ah1[4], al0[4], al1[4], bh[4], bl[4];
            LDSM4(ah0, Ah + aoff0 + sa);
            LDSM4(ah1, Ah + aoff1 + sa);
            LDSM4(al0, Al + aoff0 + sa);
            LDSM4(al1, Al + aoff1 + sa);
            LDSM4(bh,  Bh + boff + sbo);
            LDSM4(bl,  Bl + boff + sbo);
#pragma unroll
            for (int nt = 0; nt < 2; nt++) {
                MMA(acc[0][nt], ah0, bh[2 * nt], bh[2 * nt + 1]);
                MMA(acc[1][nt], ah1, bh[2 * nt], bh[2 * nt + 1]);
                MMA(acc[0][nt], ah0, bl[2 * nt], bl[2 * nt + 1]);
                MMA(acc[1][nt], ah1, bl[2 * nt], bl[2 * nt + 1]);
                MMA(acc[0][nt], al0, bh[2 * nt], bh[2 * nt + 1]);
                MMA(acc[1][nt], al1, bh[2 * nt], bh[2 * nt + 1]);
            }
        }
    }

#pragma unroll
    for (int mt = 0; mt < 2; mt++)
#pragma unroll
        for (int nt = 0; nt < 2; nt++) {
            const int gm = bm + warp_m * 32 + mt * 16 + (lane >> 2);
            const int gn = bn + warp_n * 16 + nt * 8 + 2 * (lane & 3);
            *reinterpret_cast<float2*>(&G[(size_t)gm * ldG + gn]) =
                make_float2(acc[mt][nt][0], acc[mt][nt][1]);
            *reinterpret_cast<float2*>(&G[(size_t)(gm + 8) * ldG + gn]) =
                make_float2(acc[mt][nt][2], acc[mt][nt][3]);
        }
}

// standalone step GEMMs (prologue/tail)
template <int SET>
__global__ __launch_bounds__(256, 2) void gemm_kernel()
{
    extern __shared__ __align__(128) char smem[];
    gemm_body<SET>(smem, blockIdx.x, blockIdx.y, blockIdx.z);
}

// merged: blocks x<32 run g2(t) tile x; x>=32 run g1(t+1) tile x-32.
// 3 CTAs/SM: 448 CTAs over 444 slots = 1.01 waves (was 1.51 at 2/SM).
__global__ __launch_bounds__(256, 3) void gemmstep_kernel()
{
    extern __shared__ __align__(128) char smem[];
    if (blockIdx.x < 32) gemm_body<2>(smem, blockIdx.x, blockIdx.y, blockIdx.z);
    else                 gemm_body<1>(smem, blockIdx.x - 32, blockIdx.y, blockIdx.z);
}

// --------------------- epi bodies (R7 scalar, verbatim) ----------------------
__device__ __forceinline__ void epi1_body(
    int idx, const float* __restrict__ bmih, const float* __restrict__ bmhh, int t)
{
    const int b = idx >> 9, hc = idx & 511;
    const float* __restrict__ Ga = g_G1[0] + (size_t)b * N1;
    const float* __restrict__ Gb = g_G1[1] + (size_t)b * N1;
    const float* __restrict__ Gx = g_XW + ((size_t)t * B_ + b) * N1;

    float vi = sigf (Ga[hc]        + Gb[hc]        + __ldcs(Gx + hc)        + bmih[hc]        + bmhh[hc]);
    float vo = sigf (Ga[512 + hc]  + Gb[512 + hc]  + __ldcs(Gx + 512 + hc)  + bmih[512 + hc]  + bmhh[512 + hc]);
    float vg = tanhf(Ga[1024 + hc] + Gb[1024 + hc] + __ldcs(Gx + 1024 + hc) + bmih[1024 + hc] + bmhh[1024 + hc]);

    float fs = 0.0f;
#pragma unroll
    for (int j = 1; j <= KLAG; j++)
        fs = fmaf(g_wd[j - 1][hc], g_hist[(t - j) & (KLAG - 1)][idx], fs);

    float c1 = vi * vg - fs;
    g_hist[t & (KLAG - 1)][idx] = c1;
    float h1n = vo * tanhf(c1);
    split1(h1n, g_h1hi[idx], g_h1lo[idx]);
}

__device__ __forceinline__ void epi2_body(
    int idx, const float* __restrict__ bih, const float* __restrict__ bhh,
    const int* __restrict__ length, int t)
{
    const int b = idx >> 9, hc = idx & 511;
    const float* __restrict__ Ga = g_G2[0] + (size_t)b * N2;
    const float* __restrict__ Gb = g_G2[1] + (size_t)b * N2;

    float xi = sigf (Ga[hc]        + Gb[hc]        + bih[hc]        + bhh[hc]);
    float xf = sigf (Ga[512 + hc]  + Gb[512 + hc]  + bih[512 + hc]  + bhh[512 + hc]);
    float xg = tanhf(Ga[1024 + hc] + Gb[1024 + hc] + bih[1024 + hc] + bhh[1024 + hc]);
    float xo = sigf (Ga[1536 + hc] + Gb[1536 + hc] + bih[1536 + hc] + bhh[1536 + hc]);

    float cn = xf * g_c2[idx] + xi * xg;
    g_c2[idx] = cn;
    float hv = tanhf(xo * tanhf(cn));
    split1(hv, g_h2hi[idx], g_h2lo[idx]);
    if (length[b] == t) g_sel[idx] = hv;
}

__global__ __launch_bounds__(256) void epi1_kernel(
    const float* __restrict__ bmih, const float* __restrict__ bmhh, int t)
{
    epi1_body(blockIdx.x * blockDim.x + threadIdx.x, bmih, bmhh, t);
}
__global__ __launch_bounds__(256) void epi2_kernel(
    const float* __restrict__ bih, const float* __restrict__ bhh,
    const int* __restrict__ length, int t)
{
    epi2_body(blockIdx.x * blockDim.x + threadIdx.x, bih, bhh, length, t);
}
// fused: blocks [0,512) run epi1(t+1); blocks [512,1024) run epi2(t)
__global__ __launch_bounds__(256) void epiX_kernel(
    const float* __restrict__ bmih, const float* __restrict__ bmhh,
    const float* __restrict__ bih,  const float* __restrict__ bhh,
    const int* __restrict__ length, int t)
{
    const int blk = blockIdx.x;
    if (blk < 512) {
        epi1_body(blk * blockDim.x + threadIdx.x, bmih, bmhh, t + 1);
    } else {
        epi2_body((blk - 512) * blockDim.x + threadIdx.x, bih, bhh, length, t);
    }
}

// ------------------------------- head ---------------------------------------
__global__ __launch_bounds__(128) void head_kernel(
    const float* __restrict__ Wout, const float* __restrict__ bout,
    float* __restrict__ out)
{
    const int warp = (blockIdx.x * blockDim.x + threadIdx.x) >> 5;
    const int lane = threadIdx.x & 31;
    if (warp >= B_) return;

    float p[O_] = {0.f, 0.f, 0.f, 0.f, 0.f};
    for (int h = lane; h < H_; h += 32) {
        float s = g_sel[warp * H_ + h];
#pragma unroll
        for (int o = 0; o < O_; o++) p[o] = fmaf(s, Wout[o * H_ + h], p[o]);
    }
#pragma unroll
    for (int o = 0; o < O_; o++)
#pragma unroll
        for (int off = 16; off > 0; off >>= 1)
            p[o] += __shfl_xor_sync(0xffffffffu, p[o], off);

    if (lane == 0) {
        float l[O_], m = -1e30f;
#pragma unroll
        for (int o = 0; o < O_; o++) { l[o] = p[o] + bout[o]; m = fmaxf(m, l[o]); }
        float s = 0.0f;
#pragma unroll
        for (int o = 0; o < O_; o++) s += expf(l[o] - m);
        float ls = logf(s);
#pragma unroll
        for (int o = 0; o < O_; o++) out[warp * O_ + o] = l[o] - m - ls;
    }
}

// ----------------------------- launcher -------------------------------------
extern "C" void kernel_launch(void* const* d_in, const int* in_sizes, int n_in,
                              void* d_out, int out_size)
{
    const float* x    = (const float*)d_in[0];
    const int*   len  = (const int*)  d_in[1];
    const float* b_d  = (const float*)d_in[2];
    const float* Wmih = (const float*)d_in[3];
    const float* Wmhh = (const float*)d_in[4];
    const float* bmih = (const float*)d_in[5];
    const float* bmhh = (const float*)d_in[6];
    const float* Wih  = (const float*)d_in[7];
    const float* Whh  = (const float*)d_in[8];
    const float* bih  = (const float*)d_in[9];
    const float* bhh  = (const float*)d_in[10];
    const float* Wout = (const float*)d_in[11];
    const float* bout = (const float*)d_in[12];
    float* out = (float*)d_out;

    cudaFuncSetAttribute(gemmx_kernel,    cudaFuncAttributeMaxDynamicSharedMemorySize, SMEM_X);
    cudaFuncSetAttribute(gemm_kernel<1>,  cudaFuncAttributeMaxDynamicSharedMemorySize, SMEM_S);
    cudaFuncSetAttribute(gemm_kernel<2>,  cudaFuncAttributeMaxDynamicSharedMemorySize, SMEM_S);
    cudaFuncSetAttribute(gemmstep_kernel, cudaFuncAttributeMaxDynamicSharedMemorySize, SMEM_S);

    init_kernel<<<1024, 256>>>(b_d, x, Wmih, Wmhh, Wih, Whh);

    // hoisted input projection over all timesteps (throughput GEMM)
    gemmx_kernel<<<dim3(N1 / 128, (T_ * B_) / 128), 256, SMEM_X>>>();

    // prologue: g1(0), epi1(0)
    gemm_kernel<1><<<dim3(N1 / 64, 4, 2), 256, SMEM_S>>>();
    epi1_kernel<<<BH / 256, 256>>>(bmih, bmhh, 0);

    // main loop: [g2(t) || g1(t+1)] -> [epi2(t) || epi1(t+1)]
    for (int t = 0; t < T_ - 1; t++) {
        gemmstep_kernel<<<dim3(32 + 24, 4, 2), 256, SMEM_S>>>();
        epiX_kernel<<<2 * (BH / 256), 256>>>(bmih, bmhh, bih, bhh, len, t);
    }

    // tail: g2(T-1), epi2(T-1)
    gemm_kernel<2><<<dim3(N2 / 64, 4, 2), 256, SMEM_S>>>();
    epi2_kernel<<<BH / 256, 256>>>(bih, bhh, len, T_ - 1);

    head_kernel<<<64, 128>>>(Wout, bout, out);
}